// round 7
// baseline (speedup 1.0000x reference)
#include <cuda_runtime.h>
#include <cstdint>

#define DIM_    768
#define HEADS_  12
#define DH_     64
#define INNER_  768
#define B_      4
#define SEQ_    1024
#define EPS_    1e-5f

static constexpr int  TOK  = B_ * SEQ_;          // 4096
static constexpr long NN   = (long)SEQ_ * SEQ_;  // 1M
static constexpr int  QKVW = 3 * INNER_;         // 2304

// ---------------------------------------------------------------------------
// Scratch
// ---------------------------------------------------------------------------
__device__ float g_qkv  [(size_t)TOK * QKVW];
__device__ float g_attnA[(size_t)B_ * HEADS_ * SEQ_ * SEQ_];
__device__ float g_attnB[(size_t)B_ * HEADS_ * SEQ_ * SEQ_];
__device__ float g_outh [(size_t)2 * TOK * INNER_];          // 2 K-split partials

// ---------------------------------------------------------------------------
// helpers
// ---------------------------------------------------------------------------
__device__ __forceinline__ uint32_t f2tf32(float f) {
    uint32_t u;
    asm("cvt.rna.tf32.f32 %0, %1;" : "=r"(u) : "f"(f));
    return u;
}
__device__ __forceinline__ float roundtf(float f) {
    return __uint_as_float(f2tf32(f));
}

__device__ __forceinline__ void mma_tf32(float (&d)[4],
                                         const uint32_t (&a)[4],
                                         const uint32_t (&b)[2]) {
    asm volatile(
        "mma.sync.aligned.m16n8k8.row.col.f32.tf32.tf32.f32 "
        "{%0,%1,%2,%3}, {%4,%5,%6,%7}, {%8,%9}, {%0,%1,%2,%3};\n"
        : "+f"(d[0]), "+f"(d[1]), "+f"(d[2]), "+f"(d[3])
        : "r"(a[0]), "r"(a[1]), "r"(a[2]), "r"(a[3]),
          "r"(b[0]), "r"(b[1]));
}

__device__ __forceinline__ void cpasync16(float* smem, const float* gmem) {
    uint32_t s = (uint32_t)__cvta_generic_to_shared(smem);
    asm volatile("cp.async.cg.shared.global [%0], [%1], 16;\n"
                 :: "r"(s), "l"(gmem));
}
#define CP_COMMIT() asm volatile("cp.async.commit_group;\n" ::: "memory")
template<int N> __device__ __forceinline__ void cp_wait() {
    asm volatile("cp.async.wait_group %0;\n" :: "n"(N) : "memory");
}

// ---------------------------------------------------------------------------
// tf32 tensor-core GEMM; cp.async pipeline with STAGES buffers.
//   C[m,n] = alpha * sum_k A[m,k]*B(k,n) (+ bias[n])
//   TRB: B layout. CVTA/CVTB: cvt at fragment load. ROUND: tf32-round C.
//   KSPLIT: split K across blockIdx.x%KSPLIT; partial kseg writes C+kseg*cSplit.
//   STAGEC: stage C tile in smem for coalesced float4 stores.
// Requires 256 threads; M%BM==0, N%BN==0, (K/KSPLIT)%BK==0.
// STAGES==1 requires K/KSPLIT==BK.
// ---------------------------------------------------------------------------
template<int BM, int BN, int BK, int STAGES, int WR, int WC,
         bool TRB, bool CVTA, bool CVTB, bool ROUND, int KSPLIT, bool STAGEC>
__global__ __launch_bounds__(256)
void tgemm_kernel(const float* __restrict__ A,
                  const float* __restrict__ B,
                  float*       __restrict__ C,
                  const float* __restrict__ bias,
                  int K, int lda, int ldb, int ldc,
                  long aOuter, long aInner,
                  long bOuter, long bInner,
                  long cOuter, long cInner,
                  int innerDiv, float alpha, long cSplit)
{
    constexpr int NTH  = 256;
    constexpr int MT   = BM / (WR*16);
    constexpr int NT   = BN / (WC*8);
    constexpr int ALD  = BK + 4;
    constexpr int BLD  = TRB ? (BK + 4) : (BN + 8);
    constexpr int BROW = TRB ? BN : BK;
    constexpr int ASZ  = BM * ALD;
    constexpr int BSZ  = BROW * BLD;
    constexpr int KST  = BK / 8;
    constexpr int CLD  = BN + 4;

    extern __shared__ float dynsmem[];
    float* AsAll = dynsmem;
    float* BsAll = dynsmem + STAGES*ASZ;

    const int tid  = threadIdx.x;
    const int wid  = tid >> 5;
    const int lane = tid & 31;
    const int wr   = wid / WC;
    const int wc   = wid % WC;
    const int g    = lane >> 2;
    const int tq   = lane & 3;

    const int z  = blockIdx.z;
    const int zo = z / innerDiv;
    const int zi = z % innerDiv;
    A += zo*aOuter + zi*aInner;
    B += zo*bOuter + zi*bInner;
    C += zo*cOuter + zi*cInner;

    // ---- K-split handling ----------------------------------------------
    const int bx   = blockIdx.x;
    const int kseg = (KSPLIT > 1) ? (bx % KSPLIT) : 0;
    const int col0 = ((KSPLIT > 1) ? (bx / KSPLIT) : bx) * BN;
    const int Kloc = K / KSPLIT;
    if (KSPLIT > 1) {
        const int kbase = kseg * Kloc;
        A += kbase;                               // A row-major: k contiguous
        B += TRB ? (long)kbase : (long)kbase*ldb;
        C += (long)kseg * cSplit;
    }

    const int row0 = blockIdx.y * BM;
    const int mw   = wr * (MT*16);
    const int nw   = wc * (NT*8);

    // ---- hoisted load addressing ---------------------------------------
    constexpr int A_TPR   = BK/4;
    constexpr int A_RSTEP = NTH / A_TPR;
    constexpr int AITER   = BM / A_RSTEP;
    const int aRow = tid / A_TPR;
    const int aC4  = (tid % A_TPR) * 4;
    const float* aBase = A + (long)(row0 + aRow)*lda + aC4;
    const int aSm0 = aRow*ALD + aC4;

    constexpr int B_TPR   = TRB ? (BK/4) : (BN/4);
    constexpr int B_RSTEP = NTH / B_TPR;
    constexpr int BITER   = (TRB ? BN : BK) / B_RSTEP;
    int bSm0;
    const float* bBase;
    if (!TRB) {
        const int bKr = tid / B_TPR;
        const int bC4 = (tid % B_TPR) * 4;
        bBase = B + (long)bKr*ldb + col0 + bC4;
        bSm0  = bKr*BLD + bC4;
    } else {
        const int bN  = tid / B_TPR;
        const int bC4 = (tid % B_TPR) * 4;
        bBase = B + (long)(col0 + bN)*ldb + bC4;
        bSm0  = bN*BLD + bC4;
    }

    auto issue = [&](int kt, int s) {
        const int k0 = kt * BK;
        float* AsS = AsAll + s*ASZ;
        float* BsS = BsAll + s*BSZ;
        #pragma unroll
        for (int r = 0; r < AITER; r++)
            cpasync16(&AsS[aSm0 + r*A_RSTEP*ALD],
                      aBase + (long)r*A_RSTEP*lda + k0);
        if (!TRB) {
            #pragma unroll
            for (int r = 0; r < BITER; r++)
                cpasync16(&BsS[bSm0 + r*B_RSTEP*BLD],
                          bBase + (long)(k0 + r*B_RSTEP)*ldb);
        } else {
            #pragma unroll
            for (int r = 0; r < BITER; r++)
                cpasync16(&BsS[bSm0 + r*B_RSTEP*BLD],
                          bBase + (long)r*B_RSTEP*ldb + k0);
        }
    };

    float d[MT][NT][4];
    #pragma unroll
    for (int i = 0; i < MT; i++)
        #pragma unroll
        for (int j = 0; j < NT; j++)
            #pragma unroll
            for (int r = 0; r < 4; r++) d[i][j][r] = 0.f;

    const int nk = Kloc / BK;

    auto compute = [&](int s) {
        const float* Ab = AsAll + s*ASZ;
        const float* Bb = BsAll + s*BSZ;
        #pragma unroll
        for (int kk = 0; kk < KST; kk++) {
            const int kc = kk*8;
            uint32_t a[MT][4], b[NT][2];
            #pragma unroll
            for (int mt = 0; mt < MT; mt++) {
                const int r = mw + mt*16 + g;
                float v0 = Ab[ r     *ALD + kc + tq    ];
                float v1 = Ab[(r + 8)*ALD + kc + tq    ];
                float v2 = Ab[ r     *ALD + kc + tq + 4];
                float v3 = Ab[(r + 8)*ALD + kc + tq + 4];
                a[mt][0] = CVTA ? f2tf32(v0) : __float_as_uint(v0);
                a[mt][1] = CVTA ? f2tf32(v1) : __float_as_uint(v1);
                a[mt][2] = CVTA ? f2tf32(v2) : __float_as_uint(v2);
                a[mt][3] = CVTA ? f2tf32(v3) : __float_as_uint(v3);
            }
            #pragma unroll
            for (int nt = 0; nt < NT; nt++) {
                const int c = nw + nt*8 + g;
                float v0, v1;
                if (!TRB) {
                    v0 = Bb[(kc + tq    )*BLD + c];
                    v1 = Bb[(kc + tq + 4)*BLD + c];
                } else {
                    v0 = Bb[c*BLD + kc + tq    ];
                    v1 = Bb[c*BLD + kc + tq + 4];
                }
                b[nt][0] = CVTB ? f2tf32(v0) : __float_as_uint(v0);
                b[nt][1] = CVTB ? f2tf32(v1) : __float_as_uint(v1);
            }
            #pragma unroll
            for (int mt = 0; mt < MT; mt++)
                #pragma unroll
                for (int nt = 0; nt < NT; nt++)
                    mma_tf32(d[mt][nt], a[kk == kk ? mt : mt], b[nt]);
        }
    };

    if (STAGES == 1) {
        issue(0, 0);
        CP_COMMIT();
        cp_wait<0>();
        __syncthreads();
        compute(0);
    } else {
        constexpr int PRE = STAGES - 1;
        #pragma unroll
        for (int s = 0; s < PRE; s++) {
            if (s < nk) issue(s, s);
            CP_COMMIT();
        }
        for (int i = 0; i < nk; i++) {
            cp_wait<STAGES-2>();
            __syncthreads();
            compute(i % STAGES);
            if (i + PRE < nk) issue(i + PRE, (i + PRE) % STAGES);
            CP_COMMIT();
        }
    }

    // ---- epilogue ------------------------------------------------------
    if (STAGEC) {
        float* Cs = dynsmem;                 // reuse pipeline smem
        __syncthreads();
        #pragma unroll
        for (int mt = 0; mt < MT; mt++) {
            const int r = mw + mt*16 + g;
            #pragma unroll
            for (int nt = 0; nt < NT; nt++) {
                const int c = nw + nt*8 + tq*2;
                float bx0 = 0.f, by0 = 0.f;
                if (bias) { bx0 = bias[col0 + c]; by0 = bias[col0 + c + 1]; }
                float e0 = alpha*d[mt][nt][0] + bx0;
                float e1 = alpha*d[mt][nt][1] + by0;
                float e2 = alpha*d[mt][nt][2] + bx0;
                float e3 = alpha*d[mt][nt][3] + by0;
                if (ROUND) { e0 = roundtf(e0); e1 = roundtf(e1);
                             e2 = roundtf(e2); e3 = roundtf(e3); }
                Cs[ r     *CLD + c    ] = e0;
                Cs[ r     *CLD + c + 1] = e1;
                Cs[(r + 8)*CLD + c    ] = e2;
                Cs[(r + 8)*CLD + c + 1] = e3;
            }
        }
        __syncthreads();
        constexpr int TPR = BN/4;
        constexpr int RPI = NTH/TPR;
        const int cr = tid / TPR;
        const int cc = (tid % TPR) * 4;
        #pragma unroll
        for (int r = 0; r < BM/RPI; r++) {
            float4 v = *reinterpret_cast<float4*>(&Cs[(cr + r*RPI)*CLD + cc]);
            *reinterpret_cast<float4*>(
                &C[(long)(row0 + cr + r*RPI)*ldc + col0 + cc]) = v;
        }
    } else {
        #pragma unroll
        for (int mt = 0; mt < MT; mt++) {
            const int r0 = row0 + mw + mt*16 + g;
            #pragma unroll
            for (int nt = 0; nt < NT; nt++) {
                const int c = col0 + nw + nt*8 + tq*2;
                float bx0 = 0.f, by0 = 0.f;
                if (bias) { bx0 = bias[c]; by0 = bias[c+1]; }
                float e0 = alpha*d[mt][nt][0] + bx0;
                float e1 = alpha*d[mt][nt][1] + by0;
                float e2 = alpha*d[mt][nt][2] + bx0;
                float e3 = alpha*d[mt][nt][3] + by0;
                if (ROUND) { e0 = roundtf(e0); e1 = roundtf(e1);
                             e2 = roundtf(e2); e3 = roundtf(e3); }
                float2 v0 = { e0, e1 };
                float2 v1 = { e2, e3 };
                *reinterpret_cast<float2*>(&C[(long)r0*ldc + c])     = v0;
                *reinterpret_cast<float2*>(&C[(long)(r0+8)*ldc + c]) = v1;
            }
        }
    }
}

// ---------------------------------------------------------------------------
// Elementwise: o = tf32round(a + b)   (merge K-split partials)
// ---------------------------------------------------------------------------
__global__ __launch_bounds__(256)
void addround_kernel(const float* __restrict__ a,
                     const float* __restrict__ b,
                     float*       __restrict__ o)
{
    const long i = ((long)blockIdx.x * 256 + threadIdx.x) * 4;
    float4 va = *reinterpret_cast<const float4*>(a + i);
    float4 vb = *reinterpret_cast<const float4*>(b + i);
    float4 r;
    r.x = roundtf(va.x + vb.x);
    r.y = roundtf(va.y + vb.y);
    r.z = roundtf(va.z + vb.z);
    r.w = roundtf(va.w + vb.w);
    *reinterpret_cast<float4*>(o + i) = r;
}

// ---------------------------------------------------------------------------
// Fused softmax + cross-head remix + LayerNorm. One block per (b,i).
// Output rounded to tf32.
// ---------------------------------------------------------------------------
__global__ __launch_bounds__(256)
void softmax_remix_ln_kernel(const float* __restrict__ attnA,
                             float*       __restrict__ attnB,
                             const float* __restrict__ W,
                             const float* __restrict__ gamma,
                             const float* __restrict__ beta)
{
    const int i = blockIdx.x;
    const int b = blockIdx.y;
    const int t = threadIdx.x;

    __shared__ float sW[HEADS_*HEADS_];
    __shared__ float sG[HEADS_], sBt[HEADS_];
    __shared__ float red[8][HEADS_];

    if (t < HEADS_*HEADS_) sW[t] = W[t];
    if (t < HEADS_) { sG[t] = gamma[t]; sBt[t] = beta[t]; }

    const long rowbase = (long)b * HEADS_ * NN + (long)i * SEQ_;

    float4 v[HEADS_];
    #pragma unroll
    for (int h = 0; h < HEADS_; h++)
        v[h] = *reinterpret_cast<const float4*>(attnA + rowbase + (long)h*NN + t*4);

    #pragma unroll
    for (int h = 0; h < HEADS_; h++) {
        float m = fmaxf(fmaxf(v[h].x, v[h].y), fmaxf(v[h].z, v[h].w));
        #pragma unroll
        for (int o = 16; o > 0; o >>= 1)
            m = fmaxf(m, __shfl_xor_sync(0xffffffffu, m, o));
        if ((t & 31) == 0) red[t >> 5][h] = m;
    }
    __syncthreads();
    float gm[HEADS_];
    #pragma unroll
    for (int h = 0; h < HEADS_; h++) {
        float m = red[0][h];
        #pragma unroll
        for (int w = 1; w < 8; w++) m = fmaxf(m, red[w][h]);
        gm[h] = m;
    }
    __syncthreads();

    #pragma unroll
    for (int h = 0; h < HEADS_; h++) {
        v[h].x = __expf(v[h].x - gm[h]);
        v[h].y = __expf(v[h].y - gm[h]);
        v[h].z = __expf(v[h].z - gm[h]);
        v[h].w = __expf(v[h].w - gm[h]);
        float s = v[h].x + v[h].y + v[h].z + v[h].w;
        #pragma unroll
        for (int o = 16; o > 0; o >>= 1)
            s += __shfl_xor_sync(0xffffffffu, s, o);
        if ((t & 31) == 0) red[t >> 5][h] = s;
    }
    __syncthreads();
    float inv[HEADS_];
    #pragma unroll
    for (int h = 0; h < HEADS_; h++) {
        float s = red[0][h];
        #pragma unroll
        for (int w = 1; w < 8; w++) s += red[w][h];
        inv[h] = 1.f / s;
    }

    float4 outv[HEADS_];
    #pragma unroll
    for (int u = 0; u < 4; u++) {
        float p[HEADS_];
        #pragma unroll
        for (int h = 0; h < HEADS_; h++) {
            float pv = (u == 0) ? v[h].x : (u == 1) ? v[h].y
                     : (u == 2) ? v[h].z : v[h].w;
            p[h] = pv * inv[h];
        }
        float mixed[HEADS_];
        float mu = 0.f;
        #pragma unroll
        for (int k = 0; k < HEADS_; k++) {
            float s = 0.f;
            #pragma unroll
            for (int h = 0; h < HEADS_; h++) s += p[h] * sW[h*HEADS_ + k];
            mixed[k] = s;
            mu += s;
        }
        mu *= (1.f / HEADS_);
        float var = 0.f;
        #pragma unroll
        for (int k = 0; k < HEADS_; k++) {
            const float dd = mixed[k] - mu;
            var += dd * dd;
        }
        var *= (1.f / HEADS_);
        const float ninv = rsqrtf(var + EPS_);

        #pragma unroll
        for (int k = 0; k < HEADS_; k++) {
            float r = roundtf((mixed[k] - mu) * ninv * sG[k] + sBt[k]);
            if      (u == 0) outv[k].x = r;
            else if (u == 1) outv[k].y = r;
            else if (u == 2) outv[k].z = r;
            else             outv[k].w = r;
        }
    }
    #pragma unroll
    for (int k = 0; k < HEADS_; k++)
        *reinterpret_cast<float4*>(attnB + rowbase + (long)k*NN + t*4) = outv[k];
}

// ---------------------------------------------------------------------------
// Host launcher
// ---------------------------------------------------------------------------
extern "C" void kernel_launch(void* const* d_in, const int* in_sizes, int n_in,
                              void* d_out, int out_size)
{
    const float* x       = (const float*)d_in[0];
    const float* w_qkv   = (const float*)d_in[1];
    const float* reattnW = (const float*)d_in[2];
    const float* gamma   = (const float*)d_in[3];
    const float* beta    = (const float*)d_in[4];
    const float* w_out   = (const float*)d_in[5];
    const float* b_out   = (const float*)d_in[6];
    float* out = (float*)d_out;

    float *qkv, *attnA, *attnB, *outh;
    cudaGetSymbolAddress((void**)&qkv,   g_qkv);
    cudaGetSymbolAddress((void**)&attnA, g_attnA);
    cudaGetSymbolAddress((void**)&attnB, g_attnB);
    cudaGetSymbolAddress((void**)&outh,  g_outh);

    const float scale = 0.125f;
    const long  OUTH_SPLIT = (long)TOK * INNER_;

    // smem bytes
    constexpr int SM_QKV  = 3 * (128*20 + 16*136) * 4;                  // 56,832
    constexpr int SM_DOTS = 1 * (128*68 + 128*68) * 4;                  // 69,632 (>= C stage 128*132*4)
    constexpr int SM_AV   = 4 * (64*20  + 16*72 ) * 4;                  // 38,912
    constexpr int SM_OUT  = SM_QKV;

    // 1) qkv = x @ w_qkv  (cvt both, round output -> Q,K,V tf32)
    {
        auto k = tgemm_kernel<128,128,16,3,2,4,false,true,true,true,1,false>;
        cudaFuncSetAttribute(k, cudaFuncAttributeMaxDynamicSharedMemorySize, SM_QKV);
        dim3 grid(QKVW/128, TOK/128, 1);
        k<<<grid, 256, SM_QKV>>>(
            x, w_qkv, qkv, nullptr,
            DIM_, DIM_, QKVW, QKVW,
            0,0, 0,0, 0,0, 1, 1.f, 0);
    }

    // 2) dots = scale * Q K^T per (b,h): single-shot BK=64, smem-staged C
    {
        auto k = tgemm_kernel<128,128,64,1,2,4,true,false,false,false,1,true>;
        cudaFuncSetAttribute(k, cudaFuncAttributeMaxDynamicSharedMemorySize, SM_DOTS);
        dim3 grid(SEQ_/128, SEQ_/128, B_*HEADS_);
        k<<<grid, 256, SM_DOTS>>>(
            qkv, qkv + INNER_, attnA, nullptr,
            DH_, QKVW, QKVW, SEQ_,
            (long)SEQ_*QKVW, DH_,
            (long)SEQ_*QKVW, DH_,
            (long)HEADS_*NN,  NN,
            HEADS_, scale, 0);
    }

    // 3) softmax + remix + LN -> attnB (tf32-rounded)
    {
        dim3 grid(SEQ_, B_);
        softmax_remix_ln_kernel<<<grid, 256>>>(attnA, attnB, reattnW, gamma, beta);
    }

    // 4) out_heads = attnB @ V per (b,h): K split in 2, fp32 partials
    {
        auto k = tgemm_kernel<64,64,16,4,2,4,false,false,false,false,2,false>;
        cudaFuncSetAttribute(k, cudaFuncAttributeMaxDynamicSharedMemorySize, SM_AV);
        dim3 grid(2, SEQ_/64, B_*HEADS_);
        k<<<grid, 256, SM_AV>>>(
            attnB, qkv + 2*INNER_, outh, nullptr,
            SEQ_, SEQ_, QKVW, INNER_,
            (long)HEADS_*NN, NN,
            (long)SEQ_*QKVW, DH_,
            (long)SEQ_*INNER_, DH_,
            HEADS_, 1.f, OUTH_SPLIT);
    }

    // 4b) merge partials + tf32 round (in place into first partial)
    {
        const long nfloat4 = (long)TOK * INNER_ / 4;
        addround_kernel<<<(unsigned)(nfloat4 / 256), 256>>>(
            outh, outh + OUTH_SPLIT, outh);
    }

    // 5) out = out_heads @ w_out + b_out
    {
        auto k = tgemm_kernel<128,128,16,3,2,4,false,false,true,false,1,false>;
        cudaFuncSetAttribute(k, cudaFuncAttributeMaxDynamicSharedMemorySize, SM_OUT);
        dim3 grid(INNER_/128, TOK/128, 1);
        k<<<grid, 256, SM_OUT>>>(
            outh, w_out, out, b_out,
            INNER_, INNER_, DIM_, DIM_,
            0,0, 0,0, 0,0, 1, 1.f, 0);
    }
}

// round 8
// speedup vs baseline: 1.0144x; 1.0144x over previous
#include <cuda_runtime.h>
#include <cstdint>

#define DIM_    768
#define HEADS_  12
#define DH_     64
#define INNER_  768
#define B_      4
#define SEQ_    1024
#define EPS_    1e-5f

static constexpr int  TOK  = B_ * SEQ_;          // 4096
static constexpr long NN   = (long)SEQ_ * SEQ_;  // 1M
static constexpr int  QKVW = 3 * INNER_;         // 2304

// ---------------------------------------------------------------------------
// Scratch
// ---------------------------------------------------------------------------
__device__ float g_qkv  [(size_t)TOK * QKVW];
__device__ float g_attnA[(size_t)B_ * HEADS_ * SEQ_ * SEQ_];
__device__ float g_attnB[(size_t)B_ * HEADS_ * SEQ_ * SEQ_];
__device__ float g_outh [(size_t)TOK * INNER_];

// ---------------------------------------------------------------------------
// helpers
// ---------------------------------------------------------------------------
__device__ __forceinline__ uint32_t f2tf32(float f) {
    uint32_t u;
    asm("cvt.rna.tf32.f32 %0, %1;" : "=r"(u) : "f"(f));
    return u;
}
__device__ __forceinline__ float roundtf(float f) {
    return __uint_as_float(f2tf32(f));
}
__device__ __forceinline__ uint32_t cvtbits(uint32_t u) {
    return f2tf32(__uint_as_float(u));
}

__device__ __forceinline__ void mma_tf32(float (&d)[4],
                                         const uint32_t (&a)[4],
                                         const uint32_t (&b)[2]) {
    asm volatile(
        "mma.sync.aligned.m16n8k8.row.col.f32.tf32.tf32.f32 "
        "{%0,%1,%2,%3}, {%4,%5,%6,%7}, {%8,%9}, {%0,%1,%2,%3};\n"
        : "+f"(d[0]), "+f"(d[1]), "+f"(d[2]), "+f"(d[3])
        : "r"(a[0]), "r"(a[1]), "r"(a[2]), "r"(a[3]),
          "r"(b[0]), "r"(b[1]));
}

__device__ __forceinline__ void ldsm_x4(uint32_t (&r)[4], uint32_t saddr) {
    asm volatile(
        "ldmatrix.sync.aligned.m8n8.x4.shared.b16 {%0,%1,%2,%3}, [%4];\n"
        : "=r"(r[0]), "=r"(r[1]), "=r"(r[2]), "=r"(r[3]) : "r"(saddr));
}
__device__ __forceinline__ void ldsm_x2(uint32_t (&r)[2], uint32_t saddr) {
    asm volatile(
        "ldmatrix.sync.aligned.m8n8.x2.shared.b16 {%0,%1}, [%2];\n"
        : "=r"(r[0]), "=r"(r[1]) : "r"(saddr));
}

__device__ __forceinline__ void cpasync16(float* smem, const float* gmem) {
    uint32_t s = (uint32_t)__cvta_generic_to_shared(smem);
    asm volatile("cp.async.cg.shared.global [%0], [%1], 16;\n"
                 :: "r"(s), "l"(gmem));
}
#define CP_COMMIT() asm volatile("cp.async.commit_group;\n" ::: "memory")
template<int N> __device__ __forceinline__ void cp_wait() {
    asm volatile("cp.async.wait_group %0;\n" :: "n"(N) : "memory");
}

// ---------------------------------------------------------------------------
// tf32 tensor-core GEMM; cp.async pipeline; ldmatrix fragment loads.
//   C[m,n] = alpha * sum_k A[m,k]*B(k,n) (+ bias[n])
//   TRB=false: B is [K,N] row-major (scalar B frag loads).
//   TRB=true : B is [N,K] row-major (ldmatrix B frag loads).
//   CVTA/CVTB: cvt operand to tf32 at fragment load (false => pre-rounded).
//   ROUND: round C to tf32 before store.
// 256 threads. M%BM==0, N%BN==0, K%BK==0. STAGES==1 requires K==BK.
// ---------------------------------------------------------------------------
template<int BM, int BN, int BK, int STAGES, int WR, int WC,
         bool TRB, bool CVTA, bool CVTB, bool ROUND>
__global__ __launch_bounds__(256)
void tgemm_kernel(const float* __restrict__ A,
                  const float* __restrict__ B,
                  float*       __restrict__ C,
                  const float* __restrict__ bias,
                  int K, int lda, int ldb, int ldc,
                  long aOuter, long aInner,
                  long bOuter, long bInner,
                  long cOuter, long cInner,
                  int innerDiv, float alpha)
{
    constexpr int NTH  = 256;
    constexpr int MT   = BM / (WR*16);
    constexpr int NT   = BN / (WC*8);
    constexpr int ALD  = BK + 4;
    constexpr int BLD  = TRB ? (BK + 4) : (BN + 8);
    constexpr int BROW = TRB ? BN : BK;
    constexpr int ASZ  = BM * ALD;
    constexpr int BSZ  = BROW * BLD;
    constexpr int KST  = BK / 8;

    extern __shared__ float dynsmem[];
    float* AsAll = dynsmem;
    float* BsAll = dynsmem + STAGES*ASZ;
    const uint32_t smem_u32 = (uint32_t)__cvta_generic_to_shared(dynsmem);

    const int tid  = threadIdx.x;
    const int wid  = tid >> 5;
    const int lane = tid & 31;
    const int wr   = wid / WC;
    const int wc   = wid % WC;
    const int g    = lane >> 2;
    const int tq   = lane & 3;

    const int z  = blockIdx.z;
    const int zo = z / innerDiv;
    const int zi = z % innerDiv;
    A += zo*aOuter + zi*aInner;
    B += zo*bOuter + zi*bInner;
    C += zo*cOuter + zi*cInner;

    const int row0 = blockIdx.x == blockIdx.x ? blockIdx.y * BM : 0;
    const int col0 = blockIdx.x * BN;
    const int mw   = wr * (MT*16);
    const int nw   = wc * (NT*8);

    // ---- ldmatrix per-lane byte offsets (within a stage) ----------------
    // A fragment (m16k8): 4 8x4-b32 matrices; lane -> matrix lane>>3.
    //   matrix m: rows (m&1)*8.., b32 cols (m>>1)*4..
    const int lmRow = lane & 7;
    const int lmM   = lane >> 3;          // 0..3
    uint32_t aOff[MT];
    #pragma unroll
    for (int mt = 0; mt < MT; mt++)
        aOff[mt] = ((mw + mt*16 + (lmM & 1)*8 + lmRow)*ALD + (lmM >> 1)*4) * 4;
    // B fragment (TRB, n8k8): 2 8x4-b32 matrices; x2 uses lanes 0..15.
    uint32_t bOffT[NT];
    #pragma unroll
    for (int nt = 0; nt < NT; nt++)
        bOffT[nt] = ((nw + nt*8 + lmRow)*BLD + (lmM & 1)*4) * 4;

    // ---- cp.async addressing -------------------------------------------
    constexpr int A_TPR   = BK/4;
    constexpr int A_RSTEP = NTH / A_TPR;
    constexpr int AITER   = BM / A_RSTEP;
    const int aRow = tid / A_TPR;
    const int aC4  = (tid % A_TPR) * 4;
    const float* aBase = A + (long)(row0 + aRow)*lda + aC4;
    const int aSm0 = aRow*ALD + aC4;

    constexpr int B_TPR   = TRB ? (BK/4) : (BN/4);
    constexpr int B_RSTEP = NTH / B_TPR;
    constexpr int BITER   = (TRB ? BN : BK) / B_RSTEP;
    int bSm0;
    const float* bBase;
    if (!TRB) {
        const int bKr = tid / B_TPR;
        const int bC4 = (tid % B_TPR) * 4;
        bBase = B + (long)bKr*ldb + col0 + bC4;
        bSm0  = bKr*BLD + bC4;
    } else {
        const int bN  = tid / B_TPR;
        const int bC4 = (tid % B_TPR) * 4;
        bBase = B + (long)(col0 + bN)*ldb + bC4;
        bSm0  = bN*BLD + bC4;
    }

    auto issue = [&](int kt, int s) {
        const int k0 = kt * BK;
        float* AsS = AsAll + s*ASZ;
        float* BsS = BsAll + s*BSZ;
        #pragma unroll
        for (int r = 0; r < AITER; r++)
            cpasync16(&AsS[aSm0 + r*A_RSTEP*ALD],
                      aBase + (long)r*A_RSTEP*lda + k0);
        if (!TRB) {
            #pragma unroll
            for (int r = 0; r < BITER; r++)
                cpasync16(&BsS[bSm0 + r*B_RSTEP*BLD],
                          bBase + (long)(k0 + r*B_RSTEP)*ldb);
        } else {
            #pragma unroll
            for (int r = 0; r < BITER; r++)
                cpasync16(&BsS[bSm0 + r*B_RSTEP*BLD],
                          bBase + (long)r*B_RSTEP*ldb + k0);
        }
    };

    float d[MT][NT][4];
    #pragma unroll
    for (int i = 0; i < MT; i++)
        #pragma unroll
        for (int j = 0; j < NT; j++)
            #pragma unroll
            for (int r = 0; r < 4; r++) d[i][j][r] = 0.f;

    const int nk = K / BK;

    auto compute = [&](int s) {
        const uint32_t aStage = smem_u32 + (uint32_t)(s*ASZ)*4;
        const uint32_t bStage = smem_u32 + (uint32_t)(STAGES*ASZ + s*BSZ)*4;
        const float*   Bb     = BsAll + s*BSZ;
        #pragma unroll
        for (int kk = 0; kk < KST; kk++) {
            const int kc = kk*8;
            uint32_t a[MT][4], b[NT][2];
            #pragma unroll
            for (int mt = 0; mt < MT; mt++) {
                ldsm_x4(a[mt], aStage + aOff[mt] + kc*4);
                if (CVTA) {
                    a[mt][0] = cvtbits(a[mt][0]);
                    a[mt][1] = cvtbits(a[mt][1]);
                    a[mt][2] = cvtbits(a[mt][2]);
                    a[mt][3] = cvtbits(a[mt][3]);
                }
            }
            #pragma unroll
            for (int nt = 0; nt < NT; nt++) {
                if (TRB) {
                    ldsm_x2(b[nt], bStage + bOffT[nt] + kc*4);
                } else {
                    const int c = nw + nt*8 + g;
                    b[nt][0] = __float_as_uint(Bb[(kc + tq    )*BLD + c]);
                    b[nt][1] = __float_as_uint(Bb[(kc + tq + 4)*BLD + c]);
                }
                if (CVTB) {
                    b[nt][0] = cvtbits(b[nt][0]);
                    b[nt][1] = cvtbits(b[nt][1]);
                }
            }
            #pragma unroll
            for (int mt = 0; mt < MT; mt++)
                #pragma unroll
                for (int nt = 0; nt < NT; nt++)
                    mma_tf32(d[mt][nt], a[mt], b[nt]);
        }
    };

    if (STAGES == 1) {
        issue(0, 0);
        CP_COMMIT();
        cp_wait<0>();
        __syncthreads();
        compute(0);
    } else {
        constexpr int PRE = STAGES - 1;
        #pragma unroll
        for (int s = 0; s < PRE; s++) {
            if (s < nk) issue(s, s);
            CP_COMMIT();
        }
        for (int i = 0; i < nk; i++) {
            cp_wait<STAGES-2>();
            __syncthreads();
            compute(i % STAGES);
            if (i + PRE < nk) issue(i + PRE, (i + PRE) % STAGES);
            CP_COMMIT();
        }
    }

    // ---- epilogue ------------------------------------------------------
    #pragma unroll
    for (int mt = 0; mt < MT; mt++) {
        const int r0 = row0 + mw + mt*16 + g;
        #pragma unroll
        for (int nt = 0; nt < NT; nt++) {
            const int c = col0 + nw + nt*8 + tq*2;
            float bx0 = 0.f, by0 = 0.f;
            if (bias) { bx0 = bias[c]; by0 = bias[c+1]; }
            float e0 = alpha*d[mt][nt][0] + bx0;
            float e1 = alpha*d[mt][nt][1] + by0;
            float e2 = alpha*d[mt][nt][2] + bx0;
            float e3 = alpha*d[mt][nt][3] + by0;
            if (ROUND) { e0 = roundtf(e0); e1 = roundtf(e1);
                         e2 = roundtf(e2); e3 = roundtf(e3); }
            float2 v0 = { e0, e1 };
            float2 v1 = { e2, e3 };
            *reinterpret_cast<float2*>(&C[(long)r0*ldc + c])     = v0;
            *reinterpret_cast<float2*>(&C[(long)(r0+8)*ldc + c]) = v1;
        }
    }
}

// ---------------------------------------------------------------------------
// Fused softmax + cross-head remix + LayerNorm. One block per (b,i).
// Output rounded to tf32.
// ---------------------------------------------------------------------------
__global__ __launch_bounds__(256)
void softmax_remix_ln_kernel(const float* __restrict__ attnA,
                             float*       __restrict__ attnB,
                             const float* __restrict__ W,
                             const float* __restrict__ gamma,
                             const float* __restrict__ beta)
{
    const int i = blockIdx.x;
    const int b = blockIdx.y;
    const int t = threadIdx.x;

    __shared__ float sW[HEADS_*HEADS_];
    __shared__ float sG[HEADS_], sBt[HEADS_];
    __shared__ float red[8][HEADS_];

    if (t < HEADS_*HEADS_) sW[t] = W[t];
    if (t < HEADS_) { sG[t] = gamma[t]; sBt[t] = beta[t]; }

    const long rowbase = (long)b * HEADS_ * NN + (long)i * SEQ_;

    float4 v[HEADS_];
    #pragma unroll
    for (int h = 0; h < HEADS_; h++)
        v[h] = *reinterpret_cast<const float4*>(attnA + rowbase + (long)h*NN + t*4);

    #pragma unroll
    for (int h = 0; h < HEADS_; h++) {
        float m = fmaxf(fmaxf(v[h].x, v[h].y), fmaxf(v[h].z, v[h].w));
        #pragma unroll
        for (int o = 16; o > 0; o >>= 1)
            m = fmaxf(m, __shfl_xor_sync(0xffffffffu, m, o));
        if ((t & 31) == 0) red[t >> 5][h] = m;
    }
    __syncthreads();
    float gm[HEADS_];
    #pragma unroll
    for (int h = 0; h < HEADS_; h++) {
        float m = red[0][h];
        #pragma unroll
        for (int w = 1; w < 8; w++) m = fmaxf(m, red[w][h]);
        gm[h] = m;
    }
    __syncthreads();

    #pragma unroll
    for (int h = 0; h < HEADS_; h++) {
        v[h].x = __expf(v[h].x - gm[h]);
        v[h].y = __expf(v[h].y - gm[h]);
        v[h].z = __expf(v[h].z - gm[h]);
        v[h].w = __expf(v[h].w - gm[h]);
        float s = v[h].x + v[h].y + v[h].z + v[h].w;
        #pragma unroll
        for (int o = 16; o > 0; o >>= 1)
            s += __shfl_xor_sync(0xffffffffu, s, o);
        if ((t & 31) == 0) red[t >> 5][h] = s;
    }
    __syncthreads();
    float inv[HEADS_];
    #pragma unroll
    for (int h = 0; h < HEADS_; h++) {
        float s = red[0][h];
        #pragma unroll
        for (int w = 1; w < 8; w++) s += red[w][h];
        inv[h] = 1.f / s;
    }

    float4 outv[HEADS_];
    #pragma unroll
    for (int u = 0; u < 4; u++) {
        float p[HEADS_];
        #pragma unroll
        for (int h = 0; h < HEADS_; h++) {
            float pv = (u == 0) ? v[h].x : (u == 1) ? v[h].y
                     : (u == 2) ? v[h].z : v[h].w;
            p[h] = pv * inv[h];
        }
        float mixed[HEADS_];
        float mu = 0.f;
        #pragma unroll
        for (int k = 0; k < HEADS_; k++) {
            float s = 0.f;
            #pragma unroll
            for (int h = 0; h < HEADS_; h++) s += p[h] * sW[h*HEADS_ + k];
            mixed[k] = s;
            mu += s;
        }
        mu *= (1.f / HEADS_);
        float var = 0.f;
        #pragma unroll
        for (int k = 0; k < HEADS_; k++) {
            const float dd = mixed[k] - mu;
            var += dd * dd;
        }
        var *= (1.f / HEADS_);
        const float ninv = rsqrtf(var + EPS_);

        #pragma unroll
        for (int k = 0; k < HEADS_; k++) {
            float r = roundtf((mixed[k] - mu) * ninv * sG[k] + sBt[k]);
            if      (u == 0) outv[k].x = r;
            else if (u == 1) outv[k].y = r;
            else if (u == 2) outv[k].z = r;
            else             outv[k].w = r;
        }
    }
    #pragma unroll
    for (int k = 0; k < HEADS_; k++)
        *reinterpret_cast<float4*>(attnB + rowbase + (long)k*NN + t*4) = outv[k];
}

// ---------------------------------------------------------------------------
// Host launcher
// ---------------------------------------------------------------------------
extern "C" void kernel_launch(void* const* d_in, const int* in_sizes, int n_in,
                              void* d_out, int out_size)
{
    const float* x       = (const float*)d_in[0];
    const float* w_qkv   = (const float*)d_in[1];
    const float* reattnW = (const float*)d_in[2];
    const float* gamma   = (const float*)d_in[3];
    const float* beta    = (const float*)d_in[4];
    const float* w_out   = (const float*)d_in[5];
    const float* b_out   = (const float*)d_in[6];
    float* out = (float*)d_out;

    float *qkv, *attnA, *attnB, *outh;
    cudaGetSymbolAddress((void**)&qkv,   g_qkv);
    cudaGetSymbolAddress((void**)&attnA, g_attnA);
    cudaGetSymbolAddress((void**)&attnB, g_attnB);
    cudaGetSymbolAddress((void**)&outh,  g_outh);

    const float scale = 0.125f;

    // smem bytes: STAGES * (BM*(BK+4) + BROW*BLD) * 4
    constexpr int SM_QKV  = 3 * (128*20 + 16*136) * 4;   // 56,832
    constexpr int SM_DOTS = 1 * (128*68 + 128*68) * 4;   // 69,632
    constexpr int SM_AV   = 4 * (64*20  + 16*72 ) * 4;   // 38,912
    constexpr int SM_OUT  = SM_QKV;

    // 1) qkv = x @ w_qkv  (cvt both, round output -> Q,K,V tf32)
    {
        auto k = tgemm_kernel<128,128,16,3,2,4,false,true,true,true>;
        cudaFuncSetAttribute(k, cudaFuncAttributeMaxDynamicSharedMemorySize, SM_QKV);
        dim3 grid(QKVW/128, TOK/128, 1);
        k<<<grid, 256, SM_QKV>>>(
            x, w_qkv, qkv, nullptr,
            DIM_, DIM_, QKVW, QKVW,
            0,0, 0,0, 0,0, 1, 1.f);
    }

    // 2) dots = scale * Q K^T per (b,h): single-shot BK=64, ldmatrix A+B
    {
        auto k = tgemm_kernel<128,128,64,1,2,4,true,false,false,false>;
        cudaFuncSetAttribute(k, cudaFuncAttributeMaxDynamicSharedMemorySize, SM_DOTS);
        dim3 grid(SEQ_/128, SEQ_/128, B_*HEADS_);
        k<<<grid, 256, SM_DOTS>>>(
            qkv, qkv + INNER_, attnA, nullptr,
            DH_, QKVW, QKVW, SEQ_,
            (long)SEQ_*QKVW, DH_,
            (long)SEQ_*QKVW, DH_,
            (long)HEADS_*NN,  NN,
            HEADS_, scale);
    }

    // 3) softmax + remix + LN -> attnB (tf32-rounded)
    {
        dim3 grid(SEQ_, B_);
        softmax_remix_ln_kernel<<<grid, 256>>>(attnA, attnB, reattnW, gamma, beta);
    }

    // 4) out_heads = attnB @ V per (b,h): BM=64, WR=1/WC=8 (MT=4 -> LDSM A)
    {
        auto k = tgemm_kernel<64,64,16,4,1,8,false,false,false,true>;
        cudaFuncSetAttribute(k, cudaFuncAttributeMaxDynamicSharedMemorySize, SM_AV);
        dim3 grid(1, SEQ_/64, B_*HEADS_);
        k<<<grid, 256, SM_AV>>>(
            attnB, qkv + 2*INNER_, outh, nullptr,
            SEQ_, SEQ_, QKVW, INNER_,
            (long)HEADS_*NN, NN,
            (long)SEQ_*QKVW, DH_,
            (long)SEQ_*INNER_, DH_,
            HEADS_, 1.f);
    }

    // 5) out = out_heads @ w_out + b_out
    {
        auto k = tgemm_kernel<128,128,16,3,2,4,false,false,true,false>;
        cudaFuncSetAttribute(k, cudaFuncAttributeMaxDynamicSharedMemorySize, SM_OUT);
        dim3 grid(INNER_/128, TOK/128, 1);
        k<<<grid, 256, SM_OUT>>>(
            outh, w_out, out, b_out,
            INNER_, INNER_, DIM_, DIM_,
            0,0, 0,0, 0,0, 1, 1.f);
    }
}

// round 10
// speedup vs baseline: 1.2013x; 1.1843x over previous
#include <cuda_runtime.h>
#include <cuda_fp16.h>
#include <cstdint>

#define DIM_    768
#define HEADS_  12
#define DH_     64
#define INNER_  768
#define B_      4
#define SEQ_    1024
#define EPS_    1e-5f

static constexpr int  TOK  = B_ * SEQ_;          // 4096
static constexpr long NN   = (long)SEQ_ * SEQ_;  // 1M
static constexpr int  QKVW = 3 * INNER_;         // 2304

// ---------------------------------------------------------------------------
// Scratch
// ---------------------------------------------------------------------------
__device__ float   g_qkv  [(size_t)TOK * QKVW];
__device__ float   g_attnA[(size_t)B_ * HEADS_ * SEQ_ * SEQ_];
__device__ __half  g_attnB[(size_t)B_ * HEADS_ * SEQ_ * SEQ_];
__device__ __half  g_vhf  [(size_t)TOK * INNER_];
__device__ float   g_outh [(size_t)TOK * INNER_];

// ---------------------------------------------------------------------------
// helpers
// ---------------------------------------------------------------------------
__device__ __forceinline__ uint32_t f2tf32(float f) {
    uint32_t u;
    asm("cvt.rna.tf32.f32 %0, %1;" : "=r"(u) : "f"(f));
    return u;
}
__device__ __forceinline__ float roundtf(float f) {
    return __uint_as_float(f2tf32(f));
}
__device__ __forceinline__ uint32_t cvtbits(uint32_t u) {
    return f2tf32(__uint_as_float(u));
}

__device__ __forceinline__ void mma_tf32(float (&d)[4],
                                         const uint32_t (&a)[4],
                                         const uint32_t (&b)[2]) {
    asm volatile(
        "mma.sync.aligned.m16n8k8.row.col.f32.tf32.tf32.f32 "
        "{%0,%1,%2,%3}, {%4,%5,%6,%7}, {%8,%9}, {%0,%1,%2,%3};\n"
        : "+f"(d[0]), "+f"(d[1]), "+f"(d[2]), "+f"(d[3])
        : "r"(a[0]), "r"(a[1]), "r"(a[2]), "r"(a[3]),
          "r"(b[0]), "r"(b[1]));
}

__device__ __forceinline__ void mma_f16(float (&d)[4],
                                        const uint32_t (&a)[4],
                                        const uint32_t (&b)[2]) {
    asm volatile(
        "mma.sync.aligned.m16n8k16.row.col.f32.f16.f16.f32 "
        "{%0,%1,%2,%3}, {%4,%5,%6,%7}, {%8,%9}, {%0,%1,%2,%3};\n"
        : "+f"(d[0]), "+f"(d[1]), "+f"(d[2]), "+f"(d[3])
        : "r"(a[0]), "r"(a[1]), "r"(a[2]), "r"(a[3]),
          "r"(b[0]), "r"(b[1]));
}

__device__ __forceinline__ void ldsm_x4(uint32_t (&r)[4], uint32_t saddr) {
    asm volatile(
        "ldmatrix.sync.aligned.m8n8.x4.shared.b16 {%0,%1,%2,%3}, [%4];\n"
        : "=r"(r[0]), "=r"(r[1]), "=r"(r[2]), "=r"(r[3]) : "r"(saddr));
}
__device__ __forceinline__ void ldsm_x2(uint32_t (&r)[2], uint32_t saddr) {
    asm volatile(
        "ldmatrix.sync.aligned.m8n8.x2.shared.b16 {%0,%1}, [%2];\n"
        : "=r"(r[0]), "=r"(r[1]) : "r"(saddr));
}
__device__ __forceinline__ void ldsm_x2_trans(uint32_t (&r)[2], uint32_t saddr) {
    asm volatile(
        "ldmatrix.sync.aligned.m8n8.x2.trans.shared.b16 {%0,%1}, [%2];\n"
        : "=r"(r[0]), "=r"(r[1]) : "r"(saddr));
}

__device__ __forceinline__ void cpasync16(void* smem, const void* gmem) {
    uint32_t s = (uint32_t)__cvta_generic_to_shared(smem);
    asm volatile("cp.async.cg.shared.global [%0], [%1], 16;\n"
                 :: "r"(s), "l"(gmem));
}
#define CP_COMMIT() asm volatile("cp.async.commit_group;\n" ::: "memory")
template<int N> __device__ __forceinline__ void cp_wait() {
    asm volatile("cp.async.wait_group %0;\n" :: "n"(N) : "memory");
}

// ---------------------------------------------------------------------------
// tf32 tensor-core GEMM; cp.async pipeline; ldmatrix fragment loads.
//   TRB=false: B is [K,N] row-major.  TRB=true: B is [N,K] row-major.
//   CVTA/CVTB: cvt operand to tf32 at fragment load. ROUND: tf32-round C.
//   VSPLIT: tiles with col0 >= 1536 write fp16 to vout[row][col-1536] (ld 768)
//           instead of fp32 to C (used by the qkv GEMM to emit V as fp16).
// 256 threads. STAGES==1 requires K==BK.
// ---------------------------------------------------------------------------
template<int BM, int BN, int BK, int STAGES, int WR, int WC,
         bool TRB, bool CVTA, bool CVTB, bool ROUND, bool VSPLIT>
__global__ __launch_bounds__(256)
void tgemm_kernel(const float* __restrict__ A,
                  const float* __restrict__ B,
                  float*       __restrict__ C,
                  const float* __restrict__ bias,
                  __half* __restrict__ vout,
                  int K, int lda, int ldb, int ldc,
                  long aOuter, long aInner,
                  long bOuter, long bInner,
                  long cOuter, long cInner,
                  int innerDiv, float alpha)
{
    constexpr int NTH  = 256;
    constexpr int MT   = BM / (WR*16);
    constexpr int NT   = BN / (WC*8);
    constexpr int ALD  = BK + 4;
    constexpr int BLD  = TRB ? (BK + 4) : (BN + 8);
    constexpr int BROW = TRB ? BN : BK;
    constexpr int ASZ  = BM * ALD;
    constexpr int BSZ  = BROW * BLD;
    constexpr int KST  = BK / 8;

    extern __shared__ float dynsmem[];
    float* AsAll = dynsmem;
    float* BsAll = dynsmem + STAGES*ASZ;
    const uint32_t smem_u32 = (uint32_t)__cvta_generic_to_shared(dynsmem);

    const int tid  = threadIdx.x;
    const int wid  = tid >> 5;
    const int lane = tid & 31;
    const int wr   = wid / WC;
    const int wc   = wid % WC;
    const int g    = lane >> 2;
    const int tq   = lane & 3;

    const int z  = blockIdx.z;
    const int zo = z / innerDiv;
    const int zi = z % innerDiv;
    A += zo*aOuter + zi*aInner;
    B += zo*bOuter + zi*bInner;
    C += zo*cOuter + zi*cInner;

    const int row0 = blockIdx.y * BM;
    const int col0 = blockIdx.x * BN;
    const int mw   = wr * (MT*16);
    const int nw   = wc * (NT*8);

    // ---- ldmatrix per-lane byte offsets ---------------------------------
    const int lmRow = lane & 7;
    const int lmM   = lane >> 3;
    uint32_t aOff[MT];
    #pragma unroll
    for (int mt = 0; mt < MT; mt++)
        aOff[mt] = ((mw + mt*16 + (lmM & 1)*8 + lmRow)*ALD + (lmM >> 1)*4) * 4;
    uint32_t bOffT[NT];
    #pragma unroll
    for (int nt = 0; nt < NT; nt++)
        bOffT[nt] = ((nw + nt*8 + lmRow)*BLD + (lmM & 1)*4) * 4;

    // ---- cp.async addressing -------------------------------------------
    constexpr int A_TPR   = BK/4;
    constexpr int A_RSTEP = NTH / A_TPR;
    constexpr int AITER   = BM / A_RSTEP;
    const int aRow = tid / A_TPR;
    const int aC4  = (tid % A_TPR) * 4;
    const float* aBase = A + (long)(row0 + aRow)*lda + aC4;
    const int aSm0 = aRow*ALD + aC4;

    constexpr int B_TPR   = TRB ? (BK/4) : (BN/4);
    constexpr int B_RSTEP = NTH / B_TPR;
    constexpr int BITER   = (TRB ? BN : BK) / B_RSTEP;
    int bSm0;
    const float* bBase;
    if (!TRB) {
        const int bKr = tid / B_TPR;
        const int bC4 = (tid % B_TPR) * 4;
        bBase = B + (long)bKr*ldb + col0 + bC4;
        bSm0  = bKr*BLD + bC4;
    } else {
        const int bN  = tid / B_TPR;
        const int bC4 = (tid % B_TPR) * 4;
        bBase = B + (long)(col0 + bN)*ldb + bC4;
        bSm0  = bN*BLD + bC4;
    }

    auto issue = [&](int kt, int s) {
        const int k0 = kt * BK;
        float* AsS = AsAll + s*ASZ;
        float* BsS = BsAll + s*BSZ;
        #pragma unroll
        for (int r = 0; r < AITER; r++)
            cpasync16(&AsS[aSm0 + r*A_RSTEP*ALD],
                      aBase + (long)r*A_RSTEP*lda + k0);
        if (!TRB) {
            #pragma unroll
            for (int r = 0; r < BITER; r++)
                cpasync16(&BsS[bSm0 + r*B_RSTEP*BLD],
                          bBase + (long)(k0 + r*B_RSTEP)*ldb);
        } else {
            #pragma unroll
            for (int r = 0; r < BITER; r++)
                cpasync16(&BsS[bSm0 + r*B_RSTEP*BLD],
                          bBase + (long)r*B_RSTEP*ldb + k0);
        }
    };

    float d[MT][NT][4];
    #pragma unroll
    for (int i = 0; i < MT; i++)
        #pragma unroll
        for (int j = 0; j < NT; j++)
            #pragma unroll
            for (int r = 0; r < 4; r++) d[i][j][r] = 0.f;

    const int nk = K / BK;

    auto compute = [&](int s) {
        const uint32_t aStage = smem_u32 + (uint32_t)(s*ASZ)*4;
        const uint32_t bStage = smem_u32 + (uint32_t)(STAGES*ASZ + s*BSZ)*4;
        const float*   Bb     = BsAll + s*BSZ;
        #pragma unroll
        for (int kk = 0; kk < KST; kk++) {
            const int kc = kk*8;
            uint32_t a[MT][4], b[NT][2];
            #pragma unroll
            for (int mt = 0; mt < MT; mt++) {
                ldsm_x4(a[mt], aStage + aOff[mt] + kc*4);
                if (CVTA) {
                    a[mt][0] = cvtbits(a[mt][0]);
                    a[mt][1] = cvtbits(a[mt][1]);
                    a[mt][2] = cvtbits(a[mt][2]);
                    a[mt][3] = cvtbits(a[mt][3]);
                }
            }
            #pragma unroll
            for (int nt = 0; nt < NT; nt++) {
                if (TRB) {
                    ldsm_x2(b[nt], bStage + bOffT[nt] + kc*4);
                } else {
                    const int c = nw + nt*8 + g;
                    b[nt][0] = __float_as_uint(Bb[(kc + tq    )*BLD + c]);
                    b[nt][1] = __float_as_uint(Bb[(kc + tq + 4)*BLD + c]);
                }
                if (CVTB) {
                    b[nt][0] = cvtbits(b[nt][0]);
                    b[nt][1] = cvtbits(b[nt][1]);
                }
            }
            #pragma unroll
            for (int mt = 0; mt < MT; mt++)
                #pragma unroll
                for (int nt = 0; nt < NT; nt++)
                    mma_tf32(d[mt][nt], a[mt], b[nt]);
        }
    };

    if (STAGES == 1) {
        issue(0, 0);
        CP_COMMIT();
        cp_wait<0>();
        __syncthreads();
        compute(0);
    } else {
        constexpr int PRE = STAGES - 1;
        #pragma unroll
        for (int s = 0; s < PRE; s++) {
            if (s < nk) issue(s, s);
            CP_COMMIT();
        }
        for (int i = 0; i < nk; i++) {
            cp_wait<STAGES-2>();
            __syncthreads();
            compute(i % STAGES);
            if (i + PRE < nk) issue(i + PRE, (i + PRE) % STAGES);
            CP_COMMIT();
        }
    }

    // ---- epilogue ------------------------------------------------------
    const bool toV = VSPLIT && (col0 >= 2*INNER_);
    #pragma unroll
    for (int mt = 0; mt < MT; mt++) {
        const int r0 = row0 + mw + mt*16 + g;
        #pragma unroll
        for (int nt = 0; nt < NT; nt++) {
            const int c = col0 + nw + nt*8 + tq*2;
            float bx0 = 0.f, by0 = 0.f;
            if (bias) { bx0 = bias[c]; by0 = bias[c+1]; }
            float e0 = alpha*d[mt][nt][0] + bx0;
            float e1 = alpha*d[mt][nt][1] + by0;
            float e2 = alpha*d[mt][nt][2] + bx0;
            float e3 = alpha*d[mt][nt][3] + by0;
            if (VSPLIT && toV) {
                __half2 v0 = __floats2half2_rn(e0, e1);
                __half2 v1 = __floats2half2_rn(e2, e3);
                const int vc = c - 2*INNER_;
                *reinterpret_cast<__half2*>(
                    &vout[(long)r0*INNER_ + vc])     = v0;
                *reinterpret_cast<__half2*>(
                    &vout[(long)(r0+8)*INNER_ + vc]) = v1;
            } else {
                if (ROUND) { e0 = roundtf(e0); e1 = roundtf(e1);
                             e2 = roundtf(e2); e3 = roundtf(e3); }
                float2 v0 = { e0, e1 };
                float2 v1 = { e2, e3 };
                *reinterpret_cast<float2*>(&C[(long)r0*ldc + c])     = v0;
                *reinterpret_cast<float2*>(&C[(long)(r0+8)*ldc + c]) = v1;
            }
        }
    }
}

// ---------------------------------------------------------------------------
// fp16 attn.V GEMM: out[b,i,(h,d)] = sum_j attnB[b,h,i,j] * V[b,j,(h,d)]
// A = attnB fp16 [b,h,i,j] (lda=SEQ), B = vhf fp16 [b*SEQ+j][INNER] (ldb=INNER)
// C = outh fp32 [b*SEQ+i][INNER], tf32-rounded.
// BM=128, BN=64(=DH), BK=32, 3 stages, 8 warps (WR=2, WC=4 -> MT=4, NT=2).
// grid: (1, SEQ/128, B*HEADS)
// ---------------------------------------------------------------------------
__global__ __launch_bounds__(256)
void hgemm_av_kernel(const __half* __restrict__ Ahf,
                     const __half* __restrict__ Vhf,
                     float* __restrict__ Cout)
{
    constexpr int BM = 128, BN = 64, BK = 32, STAGES = 3;
    constexpr int ALD = BK + 8;     // 40 halves
    constexpr int BLD = BN + 8;     // 72 halves
    constexpr int ASZ = BM * ALD;
    constexpr int BSZ = BK * BLD;
    constexpr int MT = 4, NT = 2;

    extern __shared__ __half hsm[];
    const uint32_t smem_u32 = (uint32_t)__cvta_generic_to_shared(hsm);

    const int tid  = threadIdx.x;
    const int wid  = tid >> 5;
    const int lane = tid & 31;
    const int wr   = wid >> 2;       // 0..1
    const int wc   = wid & 3;        // 0..3
    const int g    = lane >> 2;
    const int tq   = lane & 3;

    const int z = blockIdx.z;
    const int b = z / HEADS_;
    const int h = z % HEADS_;

    const __half* A = Ahf + (long)z * NN;
    const __half* V = Vhf + (long)b * SEQ_ * INNER_ + h * DH_;
    float* C = Cout + (long)b * SEQ_ * INNER_ + h * DH_;

    const int row0 = blockIdx.y * BM;
    const int mw   = wr * 64;
    const int nw   = wc * 16;

    // ---- ldmatrix byte offsets ------------------------------------------
    const int lmRow = lane & 7;
    uint32_t aOff[MT];
    #pragma unroll
    for (int mt = 0; mt < MT; mt++)
        aOff[mt] = (uint32_t)((mw + mt*16 + ((lane>>3)&1)*8 + lmRow)*ALD
                              + ((lane>>4)&1)*8) * 2;
    uint32_t bOff[NT];
    #pragma unroll
    for (int nt = 0; nt < NT; nt++)
        bOff[nt] = (uint32_t)((lane & 15)*BLD + nw + nt*8) * 2;

    // ---- cp.async addressing -------------------------------------------
    const int aRow = tid >> 2;            // 0..63
    const int aC8  = (tid & 3) * 8;
    const __half* aBase = A + (long)(row0 + aRow)*SEQ_ + aC8;
    const int aSm0 = aRow*ALD + aC8;

    const int bKr = tid >> 3;             // 0..31
    const int bC8 = (tid & 7) * 8;
    const __half* bBase = V + (long)bKr*INNER_ + bC8;
    const int bSm0 = bKr*BLD + bC8;

    auto issue = [&](int kt, int s) {
        const int k0 = kt * BK;
        __half* AsS = hsm + s*ASZ;
        __half* BsS = hsm + STAGES*ASZ + s*BSZ;
        #pragma unroll
        for (int r = 0; r < 2; r++)
            cpasync16(&AsS[aSm0 + r*64*ALD],
                      aBase + (long)r*64*SEQ_ + k0);
        cpasync16(&BsS[bSm0], bBase + (long)k0*INNER_);
    };

    float d[MT][NT][4];
    #pragma unroll
    for (int i = 0; i < MT; i++)
        #pragma unroll
        for (int j = 0; j < NT; j++)
            #pragma unroll
            for (int r = 0; r < 4; r++) d[i][j][r] = 0.f;

    const int nk = SEQ_ / BK;   // 32

    auto compute = [&](int s) {
        const uint32_t aStage = smem_u32 + (uint32_t)(s*ASZ)*2;
        const uint32_t bStage = smem_u32 + (uint32_t)(STAGES*ASZ + s*BSZ)*2;
        #pragma unroll
        for (int kk = 0; kk < 2; kk++) {          // two k16 steps
            uint32_t a[MT][4], bfr[NT][2];
            #pragma unroll
            for (int mt = 0; mt < MT; mt++)
                ldsm_x4(a[mt], aStage + aOff[mt] + kk*32);
            #pragma unroll
            for (int nt = 0; nt < NT; nt++)
                ldsm_x2_trans(bfr[nt], bStage + bOff[nt] + kk*16*BLD*2);
            #pragma unroll
            for (int mt = 0; mt < MT; mt++)
                #pragma unroll
                for (int nt = 0; nt < NT; nt++)
                    mma_f16(d[mt][nt], a[mt], bfr[nt]);
        }
    };

    issue(0, 0); CP_COMMIT();
    issue(1, 1); CP_COMMIT();
    for (int i = 0; i < nk; i++) {
        cp_wait<1>();
        __syncthreads();
        compute(i % STAGES);
        if (i + 2 < nk) issue(i + 2, (i + 2) % STAGES);
        CP_COMMIT();
    }

    // ---- epilogue: tf32-rounded fp32 -----------------------------------
    #pragma unroll
    for (int mt = 0; mt < MT; mt++) {
        const int r0 = row0 + mw + mt*16 + g;
        #pragma unroll
        for (int nt = 0; nt < NT; nt++) {
            const int c = nw + nt*8 + tq*2;
            float2 v0 = { roundtf(d[mt][nt][0]), roundtf(d[mt][nt][1]) };
            float2 v1 = { roundtf(d[mt][nt][2]), roundtf(d[mt][nt][3]) };
            *reinterpret_cast<float2*>(&C[(long)r0*INNER_ + c])     = v0;
            *reinterpret_cast<float2*>(&C[(long)(r0+8)*INNER_ + c]) = v1;
        }
    }
}

// ---------------------------------------------------------------------------
// Fused softmax + cross-head remix + LayerNorm. One block per (b,i).
// Reads fp32 scores; writes fp16 attention weights.
// ---------------------------------------------------------------------------
__global__ __launch_bounds__(256)
void softmax_remix_ln_kernel(const float* __restrict__ attnA,
                             __half* __restrict__ attnB,
                             const float* __restrict__ W,
                             const float* __restrict__ gamma,
                             const float* __restrict__ beta)
{
    const int i = blockIdx.x;
    const int b = blockIdx.y;
    const int t = threadIdx.x;

    __shared__ float sW[HEADS_*HEADS_];
    __shared__ float sG[HEADS_], sBt[HEADS_];
    __shared__ float red[8][HEADS_];

    if (t < HEADS_*HEADS_) sW[t] = W[t];
    if (t < HEADS_) { sG[t] = gamma[t]; sBt[t] = beta[t]; }

    const long rowbase = (long)b * HEADS_ * NN + (long)i * SEQ_;

    float4 v[HEADS_];
    #pragma unroll
    for (int h = 0; h < HEADS_; h++)
        v[h] = *reinterpret_cast<const float4*>(attnA + rowbase + (long)h*NN + t*4);

    #pragma unroll
    for (int h = 0; h < HEADS_; h++) {
        float m = fmaxf(fmaxf(v[h].x, v[h].y), fmaxf(v[h].z, v[h].w));
        #pragma unroll
        for (int o = 16; o > 0; o >>= 1)
            m = fmaxf(m, __shfl_xor_sync(0xffffffffu, m, o));
        if ((t & 31) == 0) red[t >> 5][h] = m;
    }
    __syncthreads();
    float gm[HEADS_];
    #pragma unroll
    for (int h = 0; h < HEADS_; h++) {
        float m = red[0][h];
        #pragma unroll
        for (int w = 1; w < 8; w++) m = fmaxf(m, red[w][h]);
        gm[h] = m;
    }
    __syncthreads();

    #pragma unroll
    for (int h = 0; h < HEADS_; h++) {
        v[h].x = __expf(v[h].x - gm[h]);
        v[h].y = __expf(v[h].y - gm[h]);
        v[h].z = __expf(v[h].z - gm[h]);
        v[h].w = __expf(v[h].w - gm[h]);
        float s = v[h].x + v[h].y + v[h].z + v[h].w;
        #pragma unroll
        for (int o = 16; o > 0; o >>= 1)
            s += __shfl_xor_sync(0xffffffffu, s, o);
        if ((t & 31) == 0) red[t >> 5][h] = s;
    }
    __syncthreads();
    float inv[HEADS_];
    #pragma unroll
    for (int h = 0; h < HEADS_; h++) {
        float s = red[0][h];
        #pragma unroll
        for (int w = 1; w < 8; w++) s += red[w][h];
        inv[h] = 1.f / s;
    }

    float4 outv[HEADS_];
    #pragma unroll
    for (int u = 0; u < 4; u++) {
        float p[HEADS_];
        #pragma unroll
        for (int h = 0; h < HEADS_; h++) {
            float pv = (u == 0) ? v[h].x : (u == 1) ? v[h].y
                     : (u == 2) ? v[h].z : v[h].w;
            p[h] = pv * inv[h];
        }
        float mixed[HEADS_];
        float mu = 0.f;
        #pragma unroll
        for (int k = 0; k < HEADS_; k++) {
            float s = 0.f;
            #pragma unroll
            for (int h = 0; h < HEADS_; h++) s += p[h] * sW[h*HEADS_ + k];
            mixed[k] = s;
            mu += s;
        }
        mu *= (1.f / HEADS_);
        float var = 0.f;
        #pragma unroll
        for (int k = 0; k < HEADS_; k++) {
            const float dd = mixed[k] - mu;
            var += dd * dd;
        }
        var *= (1.f / HEADS_);
        const float ninv = rsqrtf(var + EPS_);

        #pragma unroll
        for (int k = 0; k < HEADS_; k++) {
            float r = (mixed[k] - mu) * ninv * sG[k] + sBt[k];
            if      (u == 0) outv[k].x = r;
            else if (u == 1) outv[k].y = r;
            else if (u == 2) outv[k].z = r;
            else             outv[k].w = r;
        }
    }
    #pragma unroll
    for (int k = 0; k < HEADS_; k++) {
        __half2 lo = __floats2half2_rn(outv[k].x, outv[k].y);
        __half2 hi = __floats2half2_rn(outv[k].z, outv[k].w);
        uint2 packed = { *reinterpret_cast<uint32_t*>(&lo),
                         *reinterpret_cast<uint32_t*>(&hi) };
        *reinterpret_cast<uint2*>(attnB + rowbase + (long)k*NN + t*4) = packed;
    }
}

// ---------------------------------------------------------------------------
// Host launcher
// ---------------------------------------------------------------------------
extern "C" void kernel_launch(void* const* d_in, const int* in_sizes, int n_in,
                              void* d_out, int out_size)
{
    const float* x       = (const float*)d_in[0];
    const float* w_qkv   = (const float*)d_in[1];
    const float* reattnW = (const float*)d_in[2];
    const float* gamma   = (const float*)d_in[3];
    const float* beta    = (const float*)d_in[4];
    const float* w_out   = (const float*)d_in[5];
    const float* b_out   = (const float*)d_in[6];
    float* out = (float*)d_out;

    float *qkv, *attnA, *outh;
    __half *attnB, *vhf;
    cudaGetSymbolAddress((void**)&qkv,   g_qkv);
    cudaGetSymbolAddress((void**)&attnA, g_attnA);
    cudaGetSymbolAddress((void**)&attnB, g_attnB);
    cudaGetSymbolAddress((void**)&vhf,   g_vhf);
    cudaGetSymbolAddress((void**)&outh,  g_outh);

    const float scale = 0.125f;

    constexpr int SM_QKV  = 3 * (128*20 + 16*136) * 4;   // 56,832
    constexpr int SM_DOTS = 1 * (128*68 + 128*68) * 4;   // 69,632
    constexpr int SM_AVH  = 3 * (128*40 + 32*72) * 2;    // 44,544
    constexpr int SM_OUT  = SM_QKV;

    // 1) qkv = x @ w_qkv; Q,K tf32-rounded fp32, V emitted fp16 to vhf
    {
        auto k = tgemm_kernel<128,128,16,3,2,4,false,true,true,true,true>;
        cudaFuncSetAttribute(k, cudaFuncAttributeMaxDynamicSharedMemorySize, SM_QKV);
        dim3 grid(QKVW/128, TOK/128, 1);
        k<<<grid, 256, SM_QKV>>>(
            x, w_qkv, qkv, nullptr, vhf,
            DIM_, DIM_, QKVW, QKVW,
            0,0, 0,0, 0,0, 1, 1.f);
    }

    // 2) dots = scale * Q K^T per (b,h): single-shot BK=64, ldmatrix A+B
    {
        auto k = tgemm_kernel<128,128,64,1,2,4,true,false,false,false,false>;
        cudaFuncSetAttribute(k, cudaFuncAttributeMaxDynamicSharedMemorySize, SM_DOTS);
        dim3 grid(SEQ_/128, SEQ_/128, B_*HEADS_);
        k<<<grid, 256, SM_DOTS>>>(
            qkv, qkv + INNER_, attnA, nullptr, nullptr,
            DH_, QKVW, QKVW, SEQ_,
            (long)SEQ_*QKVW, DH_,
            (long)SEQ_*QKVW, DH_,
            (long)HEADS_*NN,  NN,
            HEADS_, scale);
    }

    // 3) softmax + remix + LN -> attnB (fp16)
    {
        dim3 grid(SEQ_, B_);
        softmax_remix_ln_kernel<<<grid, 256>>>(attnA, attnB, reattnW, gamma, beta);
    }

    // 4) out_heads = attnB @ V per (b,h): fp16 MMA
    {
        cudaFuncSetAttribute(hgemm_av_kernel,
                             cudaFuncAttributeMaxDynamicSharedMemorySize, SM_AVH);
        dim3 grid(1, SEQ_/128, B_*HEADS_);
        hgemm_av_kernel<<<grid, 256, SM_AVH>>>(attnB, vhf, outh);
    }

    // 5) out = out_heads @ w_out + b_out
    {
        auto k = tgemm_kernel<128,128,16,3,2,4,false,false,true,false,false>;
        cudaFuncSetAttribute(k, cudaFuncAttributeMaxDynamicSharedMemorySize, SM_OUT);
        dim3 grid(INNER_/128, TOK/128, 1);
        k<<<grid, 256, SM_OUT>>>(
            outh, w_out, out, b_out, nullptr,
            INNER_, INNER_, DIM_, DIM_,
            0,0, 0,0, 0,0, 1, 1.f);
    }
}

// round 11
// speedup vs baseline: 1.5514x; 1.2914x over previous
#include <cuda_runtime.h>
#include <cuda_fp16.h>
#include <cstdint>

#define DIM_    768
#define HEADS_  12
#define DH_     64
#define INNER_  768
#define B_      4
#define SEQ_    1024
#define EPS_    1e-5f

static constexpr int  TOK  = B_ * SEQ_;          // 4096
static constexpr long NN   = (long)SEQ_ * SEQ_;  // 1M
static constexpr int  QKVW = 3 * INNER_;         // 2304

// ---------------------------------------------------------------------------
// Scratch
// ---------------------------------------------------------------------------
__device__ __half  g_xh   [(size_t)TOK * DIM_];
__device__ __half  g_wqkvh[(size_t)DIM_ * QKVW];
__device__ __half  g_wouth[(size_t)INNER_ * DIM_];
__device__ __half  g_qkvh [(size_t)TOK * QKVW];
__device__ float   g_attnA[(size_t)B_ * HEADS_ * SEQ_ * SEQ_];
__device__ __half  g_attnB[(size_t)B_ * HEADS_ * SEQ_ * SEQ_];
__device__ __half  g_outh [(size_t)TOK * INNER_];

// ---------------------------------------------------------------------------
// helpers
// ---------------------------------------------------------------------------
__device__ __forceinline__ void mma_f16(float (&d)[4],
                                        const uint32_t (&a)[4],
                                        const uint32_t (&b)[2]) {
    asm volatile(
        "mma.sync.aligned.m16n8k16.row.col.f32.f16.f16.f32 "
        "{%0,%1,%2,%3}, {%4,%5,%6,%7}, {%8,%9}, {%0,%1,%2,%3};\n"
        : "+f"(d[0]), "+f"(d[1]), "+f"(d[2]), "+f"(d[3])
        : "r"(a[0]), "r"(a[1]), "r"(a[2]), "r"(a[3]),
          "r"(b[0]), "r"(b[1]));
}

__device__ __forceinline__ void ldsm_x4(uint32_t (&r)[4], uint32_t saddr) {
    asm volatile(
        "ldmatrix.sync.aligned.m8n8.x4.shared.b16 {%0,%1,%2,%3}, [%4];\n"
        : "=r"(r[0]), "=r"(r[1]), "=r"(r[2]), "=r"(r[3]) : "r"(saddr));
}
__device__ __forceinline__ void ldsm_x2(uint32_t (&r)[2], uint32_t saddr) {
    asm volatile(
        "ldmatrix.sync.aligned.m8n8.x2.shared.b16 {%0,%1}, [%2];\n"
        : "=r"(r[0]), "=r"(r[1]) : "r"(saddr));
}
__device__ __forceinline__ void ldsm_x2_trans(uint32_t (&r)[2], uint32_t saddr) {
    asm volatile(
        "ldmatrix.sync.aligned.m8n8.x2.trans.shared.b16 {%0,%1}, [%2];\n"
        : "=r"(r[0]), "=r"(r[1]) : "r"(saddr));
}

__device__ __forceinline__ void cpasync16(void* smem, const void* gmem) {
    uint32_t s = (uint32_t)__cvta_generic_to_shared(smem);
    asm volatile("cp.async.cg.shared.global [%0], [%1], 16;\n"
                 :: "r"(s), "l"(gmem));
}
#define CP_COMMIT() asm volatile("cp.async.commit_group;\n" ::: "memory")
template<int N> __device__ __forceinline__ void cp_wait() {
    asm volatile("cp.async.wait_group %0;\n" :: "n"(N) : "memory");
}

// ---------------------------------------------------------------------------
// fp32 -> fp16 conversion (1024 elements per 256-thread block)
// ---------------------------------------------------------------------------
__global__ __launch_bounds__(256)
void f2h_kernel(const float* __restrict__ src, __half* __restrict__ dst)
{
    const long i = ((long)blockIdx.x * 256 + threadIdx.x) * 4;
    float4 v = *reinterpret_cast<const float4*>(src + i);
    __half2 lo = __floats2half2_rn(v.x, v.y);
    __half2 hi = __floats2half2_rn(v.z, v.w);
    uint2 p = { *reinterpret_cast<uint32_t*>(&lo),
                *reinterpret_cast<uint32_t*>(&hi) };
    *reinterpret_cast<uint2*>(dst + i) = p;
}

// ---------------------------------------------------------------------------
// fp16 tensor-core GEMM (m16n8k16, fp32 accumulate); cp.async pipeline;
// ldmatrix fragments on both operands.
//   C[m,n] = alpha * sum_k A[m,k]*B(k,n) (+ bias[n])
//   TRB=false: B is [K,N] row-major (ldsm_x2_trans).
//   TRB=true : B is [N,K] row-major (ldsm_x2).
//   OUT16: store C as fp16 (__half2), else fp32 (float2, with bias).
// 256 threads. M%BM==0, N%BN==0, K%BK==0, BK%16==0.
// STAGES==1 requires K==BK.
// ---------------------------------------------------------------------------
template<int BM, int BN, int BK, int STAGES, int WR, int WC,
         bool TRB, bool OUT16>
__global__ __launch_bounds__(256)
void hgemm_kernel(const __half* __restrict__ A,
                  const __half* __restrict__ B,
                  void*         __restrict__ Cv,
                  const float*  __restrict__ bias,
                  int K, int lda, int ldb, int ldc,
                  long aOuter, long aInner,
                  long bOuter, long bInner,
                  long cOuter, long cInner,
                  int innerDiv, float alpha)
{
    constexpr int NTH  = 256;
    constexpr int MT   = BM / (WR*16);
    constexpr int NT   = BN / (WC*8);
    constexpr int ALD  = BK + 8;                  // halves
    constexpr int BLD  = TRB ? (BK + 8) : (BN + 8);
    constexpr int BROW = TRB ? BN : BK;
    constexpr int ASZ  = BM * ALD;                // halves
    constexpr int BSZ  = BROW * BLD;
    constexpr int KST  = BK / 16;

    extern __shared__ __half hsm[];
    const uint32_t smem_u32 = (uint32_t)__cvta_generic_to_shared(hsm);

    const int tid  = threadIdx.x;
    const int wid  = tid >> 5;
    const int lane = tid & 31;
    const int wr   = wid / WC;
    const int wc   = wid % WC;
    const int g    = lane >> 2;
    const int tq   = lane & 3;

    const int z  = blockIdx.z;
    const int zo = z / innerDiv;
    const int zi = z % innerDiv;
    A += zo*aOuter + zi*aInner;
    B += zo*bOuter + zi*bInner;

    float*  Cf = (float*)Cv  + zo*cOuter + zi*cInner;
    __half* Ch = (__half*)Cv + zo*cOuter + zi*cInner;

    const int row0 = blockIdx.y * BM;
    const int col0 = blockIdx.x * BN;
    const int mw   = wr * (MT*16);
    const int nw   = wc * (NT*8);

    // ---- ldmatrix per-lane byte offsets ---------------------------------
    uint32_t aOff[MT];
    #pragma unroll
    for (int mt = 0; mt < MT; mt++)
        aOff[mt] = (uint32_t)((mw + mt*16 + ((lane>>3)&1)*8 + (lane&7))*ALD
                              + ((lane>>4)&1)*8) * 2;
    uint32_t bOff[NT];
    #pragma unroll
    for (int nt = 0; nt < NT; nt++) {
        if (TRB)
            bOff[nt] = (uint32_t)((nw + nt*8 + (lane&7))*BLD
                                  + ((lane>>3)&1)*8) * 2;
        else
            bOff[nt] = (uint32_t)((lane & 15)*BLD + nw + nt*8) * 2;
    }

    // ---- cp.async addressing (8 halves = 16B per op) --------------------
    constexpr int A_TPR   = BK/8;
    constexpr int A_RSTEP = NTH / A_TPR;
    constexpr int AITER   = BM / A_RSTEP;
    const int aRow = tid / A_TPR;
    const int aC8  = (tid % A_TPR) * 8;
    const __half* aBase = A + (long)(row0 + aRow)*lda + aC8;
    const int aSm0 = aRow*ALD + aC8;

    constexpr int B_TPR   = TRB ? (BK/8) : (BN/8);
    constexpr int B_RSTEP = NTH / B_TPR;
    constexpr int BITER   = (TRB ? BN : BK) / B_RSTEP;
    int bSm0;
    const __half* bBase;
    if (!TRB) {
        const int bKr = tid / B_TPR;
        const int bC8 = (tid % B_TPR) * 8;
        bBase = B + (long)bKr*ldb + col0 + bC8;
        bSm0  = bKr*BLD + bC8;
    } else {
        const int bN  = tid / B_TPR;
        const int bC8 = (tid % B_TPR) * 8;
        bBase = B + (long)(col0 + bN)*ldb + bC8;
        bSm0  = bN*BLD + bC8;
    }

    auto issue = [&](int kt, int s) {
        const int k0 = kt * BK;
        __half* AsS = hsm + s*ASZ;
        __half* BsS = hsm + STAGES*ASZ + s*BSZ;
        #pragma unroll
        for (int r = 0; r < AITER; r++)
            cpasync16(&AsS[aSm0 + r*A_RSTEP*ALD],
                      aBase + (long)r*A_RSTEP*lda + k0);
        if (!TRB) {
            #pragma unroll
            for (int r = 0; r < BITER; r++)
                cpasync16(&BsS[bSm0 + r*B_RSTEP*BLD],
                          bBase + (long)(k0 + r*B_RSTEP)*ldb);
        } else {
            #pragma unroll
            for (int r = 0; r < BITER; r++)
                cpasync16(&BsS[bSm0 + r*B_RSTEP*BLD],
                          bBase + (long)r*B_RSTEP*ldb + k0);
        }
    };

    float d[MT][NT][4];
    #pragma unroll
    for (int i = 0; i < MT; i++)
        #pragma unroll
        for (int j = 0; j < NT; j++)
            #pragma unroll
            for (int r = 0; r < 4; r++) d[i][j][r] = 0.f;

    const int nk = K / BK;

    auto compute = [&](int s) {
        const uint32_t aStage = smem_u32 + (uint32_t)(s*ASZ)*2;
        const uint32_t bStage = smem_u32 + (uint32_t)(STAGES*ASZ + s*BSZ)*2;
        #pragma unroll
        for (int kk = 0; kk < KST; kk++) {
            uint32_t a[MT][4], b[NT][2];
            #pragma unroll
            for (int mt = 0; mt < MT; mt++)
                ldsm_x4(a[mt], aStage + aOff[mt] + kk*32);       // 16 halves
            #pragma unroll
            for (int nt = 0; nt < NT; nt++) {
                if (TRB)
                    ldsm_x2(b[nt], bStage + bOff[nt] + kk*32);
                else
                    ldsm_x2_trans(b[nt], bStage + bOff[nt] + kk*16*BLD*2);
            }
            #pragma unroll
            for (int mt = 0; mt < MT; mt++)
                #pragma unroll
                for (int nt = 0; nt < NT; nt++)
                    mma_f16(d[mt][nt], a[mt], b[nt]);
        }
    };

    if (STAGES == 1) {
        issue(0, 0);
        CP_COMMIT();
        cp_wait<0>();
        __syncthreads();
        compute(0);
    } else {
        constexpr int PRE = STAGES - 1;
        #pragma unroll
        for (int s = 0; s < PRE; s++) {
            if (s < nk) issue(s, s);
            CP_COMMIT();
        }
        for (int i = 0; i < nk; i++) {
            cp_wait<STAGES-2>();
            __syncthreads();
            compute(i % STAGES);
            if (i + PRE < nk) issue(i + PRE, (i + PRE) % STAGES);
            CP_COMMIT();
        }
    }

    // ---- epilogue ------------------------------------------------------
    #pragma unroll
    for (int mt = 0; mt < MT; mt++) {
        const int r0 = row0 + mw + mt*16 + g;
        #pragma unroll
        for (int nt = 0; nt < NT; nt++) {
            const int c = col0 + nw + nt*8 + tq*2;
            float e0 = alpha*d[mt][nt][0];
            float e1 = alpha*d[mt][nt][1];
            float e2 = alpha*d[mt][nt][2];
            float e3 = alpha*d[mt][nt][3];
            if (OUT16) {
                __half2 v0 = __floats2half2_rn(e0, e1);
                __half2 v1 = __floats2half2_rn(e2, e3);
                *reinterpret_cast<__half2*>(&Ch[(long)r0*ldc + c])     = v0;
                *reinterpret_cast<__half2*>(&Ch[(long)(r0+8)*ldc + c]) = v1;
            } else {
                if (bias) {
                    const float bx = bias[c], by = bias[c+1];
                    e0 += bx; e1 += by; e2 += bx; e3 += by;
                }
                float2 v0 = { e0, e1 };
                float2 v1 = { e2, e3 };
                *reinterpret_cast<float2*>(&Cf[(long)r0*ldc + c])     = v0;
                *reinterpret_cast<float2*>(&Cf[(long)(r0+8)*ldc + c]) = v1;
            }
        }
    }
}

// ---------------------------------------------------------------------------
// Fused softmax + cross-head remix + LayerNorm. One block per (b,i).
// Reads fp32 scores; writes fp16 attention weights.
// ---------------------------------------------------------------------------
__global__ __launch_bounds__(256)
void softmax_remix_ln_kernel(const float* __restrict__ attnA,
                             __half* __restrict__ attnB,
                             const float* __restrict__ W,
                             const float* __restrict__ gamma,
                             const float* __restrict__ beta)
{
    const int i = blockIdx.x;
    const int b = blockIdx.y;
    const int t = threadIdx.x;

    __shared__ float sW[HEADS_*HEADS_];
    __shared__ float sG[HEADS_], sBt[HEADS_];
    __shared__ float red[8][HEADS_];

    if (t < HEADS_*HEADS_) sW[t] = W[t];
    if (t < HEADS_) { sG[t] = gamma[t]; sBt[t] = beta[t]; }

    const long rowbase = (long)b * HEADS_ * NN + (long)i * SEQ_;

    float4 v[HEADS_];
    #pragma unroll
    for (int h = 0; h < HEADS_; h++)
        v[h] = *reinterpret_cast<const float4*>(attnA + rowbase + (long)h*NN + t*4);

    #pragma unroll
    for (int h = 0; h < HEADS_; h++) {
        float m = fmaxf(fmaxf(v[h].x, v[h].y), fmaxf(v[h].z, v[h].w));
        #pragma unroll
        for (int o = 16; o > 0; o >>= 1)
            m = fmaxf(m, __shfl_xor_sync(0xffffffffu, m, o));
        if ((t & 31) == 0) red[t >> 5][h] = m;
    }
    __syncthreads();
    float gm[HEADS_];
    #pragma unroll
    for (int h = 0; h < HEADS_; h++) {
        float m = red[0][h];
        #pragma unroll
        for (int w = 1; w < 8; w++) m = fmaxf(m, red[w][h]);
        gm[h] = m;
    }
    __syncthreads();

    #pragma unroll
    for (int h = 0; h < HEADS_; h++) {
        v[h].x = __expf(v[h].x - gm[h]);
        v[h].y = __expf(v[h].y - gm[h]);
        v[h].z = __expf(v[h].z - gm[h]);
        v[h].w = __expf(v[h].w - gm[h]);
        float s = v[h].x + v[h].y + v[h].z + v[h].w;
        #pragma unroll
        for (int o = 16; o > 0; o >>= 1)
            s += __shfl_xor_sync(0xffffffffu, s, o);
        if ((t & 31) == 0) red[t >> 5][h] = s;
    }
    __syncthreads();
    float inv[HEADS_];
    #pragma unroll
    for (int h = 0; h < HEADS_; h++) {
        float s = red[0][h];
        #pragma unroll
        for (int w = 1; w < 8; w++) s += red[w][h];
        inv[h] = 1.f / s;
    }

    float4 outv[HEADS_];
    #pragma unroll
    for (int u = 0; u < 4; u++) {
        float p[HEADS_];
        #pragma unroll
        for (int h = 0; h < HEADS_; h++) {
            float pv = (u == 0) ? v[h].x : (u == 1) ? v[h].y
                     : (u == 2) ? v[h].z : v[h].w;
            p[h] = pv * inv[h];
        }
        float mixed[HEADS_];
        float mu = 0.f;
        #pragma unroll
        for (int k = 0; k < HEADS_; k++) {
            float s = 0.f;
            #pragma unroll
            for (int h = 0; h < HEADS_; h++) s += p[h] * sW[h*HEADS_ + k];
            mixed[k] = s;
            mu += s;
        }
        mu *= (1.f / HEADS_);
        float var = 0.f;
        #pragma unroll
        for (int k = 0; k < HEADS_; k++) {
            const float dd = mixed[k] - mu;
            var += dd * dd;
        }
        var *= (1.f / HEADS_);
        const float ninv = rsqrtf(var + EPS_);

        #pragma unroll
        for (int k = 0; k < HEADS_; k++) {
            float r = (mixed[k] - mu) * ninv * sG[k] + sBt[k];
            if      (u == 0) outv[k].x = r;
            else if (u == 1) outv[k].y = r;
            else if (u == 2) outv[k].z = r;
            else             outv[k].w = r;
        }
    }
    #pragma unroll
    for (int k = 0; k < HEADS_; k++) {
        __half2 lo = __floats2half2_rn(outv[k].x, outv[k].y);
        __half2 hi = __floats2half2_rn(outv[k].z, outv[k].w);
        uint2 packed = { *reinterpret_cast<uint32_t*>(&lo),
                         *reinterpret_cast<uint32_t*>(&hi) };
        *reinterpret_cast<uint2*>(attnB + rowbase + (long)k*NN + t*4) = packed;
    }
}

// ---------------------------------------------------------------------------
// Host launcher
// ---------------------------------------------------------------------------
extern "C" void kernel_launch(void* const* d_in, const int* in_sizes, int n_in,
                              void* d_out, int out_size)
{
    const float* x       = (const float*)d_in[0];
    const float* w_qkv   = (const float*)d_in[1];
    const float* reattnW = (const float*)d_in[2];
    const float* gamma   = (const float*)d_in[3];
    const float* beta    = (const float*)d_in[4];
    const float* w_out   = (const float*)d_in[5];
    const float* b_out   = (const float*)d_in[6];
    float* out = (float*)d_out;

    __half *xh, *wqkvh, *wouth, *qkvh, *attnB, *outh;
    float  *attnA;
    cudaGetSymbolAddress((void**)&xh,    g_xh);
    cudaGetSymbolAddress((void**)&wqkvh, g_wqkvh);
    cudaGetSymbolAddress((void**)&wouth, g_wouth);
    cudaGetSymbolAddress((void**)&qkvh,  g_qkvh);
    cudaGetSymbolAddress((void**)&attnA, g_attnA);
    cudaGetSymbolAddress((void**)&attnB, g_attnB);
    cudaGetSymbolAddress((void**)&outh,  g_outh);

    const float scale = 0.125f;

    // smem bytes: STAGES*(BM*(BK+8) + BROW*BLD)*2
    constexpr int SM_QKV  = 3 * (128*40 + 32*136) * 2;   // 56,832
    constexpr int SM_DOTS = 1 * (128*72 + 128*72) * 2;   // 36,864
    constexpr int SM_AV   = 3 * (128*40 + 32*72)  * 2;   // 44,544
    constexpr int SM_OUT  = SM_QKV;

    // 0) fp32 -> fp16 conversions
    f2h_kernel<<<(TOK*DIM_)/1024,    256>>>(x,     xh);
    f2h_kernel<<<(DIM_*QKVW)/1024,   256>>>(w_qkv, wqkvh);
    f2h_kernel<<<(INNER_*DIM_)/1024, 256>>>(w_out, wouth);

    // 1) qkvh = xh @ wqkvh (fp16 out)
    {
        auto k = hgemm_kernel<128,128,32,3,2,4,false,true>;
        cudaFuncSetAttribute(k, cudaFuncAttributeMaxDynamicSharedMemorySize, SM_QKV);
        dim3 grid(QKVW/128, TOK/128, 1);
        k<<<grid, 256, SM_QKV>>>(
            xh, wqkvh, qkvh, nullptr,
            DIM_, DIM_, QKVW, QKVW,
            0,0, 0,0, 0,0, 1, 1.f);
    }

    // 2) dots = scale * Q K^T per (b,h): single-shot BK=64, fp32 out
    {
        auto k = hgemm_kernel<128,128,64,1,2,4,true,false>;
        cudaFuncSetAttribute(k, cudaFuncAttributeMaxDynamicSharedMemorySize, SM_DOTS);
        dim3 grid(SEQ_/128, SEQ_/128, B_*HEADS_);
        k<<<grid, 256, SM_DOTS>>>(
            qkvh, qkvh + INNER_, attnA, nullptr,
            DH_, QKVW, QKVW, SEQ_,
            (long)SEQ_*QKVW, DH_,
            (long)SEQ_*QKVW, DH_,
            (long)HEADS_*NN,  NN,
            HEADS_, scale);
    }

    // 3) softmax + remix + LN -> attnB (fp16)
    {
        dim3 grid(SEQ_, B_);
        softmax_remix_ln_kernel<<<grid, 256>>>(attnA, attnB, reattnW, gamma, beta);
    }

    // 4) outh = attnB @ V per (b,h) (fp16 out)
    {
        auto k = hgemm_kernel<128,64,32,3,2,4,false,true>;
        cudaFuncSetAttribute(k, cudaFuncAttributeMaxDynamicSharedMemorySize, SM_AV);
        dim3 grid(1, SEQ_/128, B_*HEADS_);
        k<<<grid, 256, SM_AV>>>(
            attnB, qkvh + 2*INNER_, outh, nullptr,
            SEQ_, SEQ_, QKVW, INNER_,
            (long)HEADS_*NN, NN,
            (long)SEQ_*QKVW, DH_,
            (long)SEQ_*INNER_, DH_,
            HEADS_, 1.f);
    }

    // 5) out = outh @ wouth + b_out (fp32 out)
    {
        auto k = hgemm_kernel<128,128,32,3,2,4,false,false>;
        cudaFuncSetAttribute(k, cudaFuncAttributeMaxDynamicSharedMemorySize, SM_OUT);
        dim3 grid(DIM_/128, TOK/128, 1);
        k<<<grid, 256, SM_OUT>>>(
            outh, wouth, out, b_out,
            INNER_, INNER_, DIM_, DIM_,
            0,0, 0,0, 0,0, 1, 1.f);
    }
}

// round 12
// speedup vs baseline: 1.6596x; 1.0698x over previous
#include <cuda_runtime.h>
#include <cuda_fp16.h>
#include <cstdint>

#define DIM_    768
#define HEADS_  12
#define DH_     64
#define INNER_  768
#define B_      4
#define SEQ_    1024
#define EPS_    1e-5f

static constexpr int  TOK  = B_ * SEQ_;          // 4096
static constexpr long NN   = (long)SEQ_ * SEQ_;  // 1M
static constexpr int  QKVW = 3 * INNER_;         // 2304

// ---------------------------------------------------------------------------
// Scratch
// ---------------------------------------------------------------------------
__device__ __half  g_xh   [(size_t)TOK * DIM_];
__device__ __half  g_wqkvh[(size_t)DIM_ * QKVW];
__device__ __half  g_wouth[(size_t)INNER_ * DIM_];
__device__ __half  g_qkvh [(size_t)TOK * QKVW];
__device__ __half  g_attnA[(size_t)B_ * HEADS_ * SEQ_ * SEQ_];   // fp16 scores
__device__ __half  g_attnB[(size_t)B_ * HEADS_ * SEQ_ * SEQ_];   // fp16 weights
__device__ __half  g_outh [(size_t)TOK * INNER_];

// ---------------------------------------------------------------------------
// helpers
// ---------------------------------------------------------------------------
__device__ __forceinline__ void mma_f16(float (&d)[4],
                                        const uint32_t (&a)[4],
                                        const uint32_t (&b)[2]) {
    asm volatile(
        "mma.sync.aligned.m16n8k16.row.col.f32.f16.f16.f32 "
        "{%0,%1,%2,%3}, {%4,%5,%6,%7}, {%8,%9}, {%0,%1,%2,%3};\n"
        : "+f"(d[0]), "+f"(d[1]), "+f"(d[2]), "+f"(d[3])
        : "r"(a[0]), "r"(a[1]), "r"(a[2]), "r"(a[3]),
          "r"(b[0]), "r"(b[1]));
}

__device__ __forceinline__ void ldsm_x4(uint32_t (&r)[4], uint32_t saddr) {
    asm volatile(
        "ldmatrix.sync.aligned.m8n8.x4.shared.b16 {%0,%1,%2,%3}, [%4];\n"
        : "=r"(r[0]), "=r"(r[1]), "=r"(r[2]), "=r"(r[3]) : "r"(saddr));
}
__device__ __forceinline__ void ldsm_x2(uint32_t (&r)[2], uint32_t saddr) {
    asm volatile(
        "ldmatrix.sync.aligned.m8n8.x2.shared.b16 {%0,%1}, [%2];\n"
        : "=r"(r[0]), "=r"(r[1]) : "r"(saddr));
}
__device__ __forceinline__ void ldsm_x2_trans(uint32_t (&r)[2], uint32_t saddr) {
    asm volatile(
        "ldmatrix.sync.aligned.m8n8.x2.trans.shared.b16 {%0,%1}, [%2];\n"
        : "=r"(r[0]), "=r"(r[1]) : "r"(saddr));
}

__device__ __forceinline__ void cpasync16(void* smem, const void* gmem) {
    uint32_t s = (uint32_t)__cvta_generic_to_shared(smem);
    asm volatile("cp.async.cg.shared.global [%0], [%1], 16;\n"
                 :: "r"(s), "l"(gmem));
}
#define CP_COMMIT() asm volatile("cp.async.commit_group;\n" ::: "memory")
template<int N> __device__ __forceinline__ void cp_wait() {
    asm volatile("cp.async.wait_group %0;\n" :: "n"(N) : "memory");
}

// ---------------------------------------------------------------------------
// fp32 -> fp16 conversion
// ---------------------------------------------------------------------------
__global__ __launch_bounds__(256)
void f2h_kernel(const float* __restrict__ src, __half* __restrict__ dst)
{
    const long i = ((long)blockIdx.x * 256 + threadIdx.x) * 4;
    float4 v = *reinterpret_cast<const float4*>(src + i);
    __half2 lo = __floats2half2_rn(v.x, v.y);
    __half2 hi = __floats2half2_rn(v.z, v.w);
    uint2 p = { *reinterpret_cast<uint32_t*>(&lo),
                *reinterpret_cast<uint32_t*>(&hi) };
    *reinterpret_cast<uint2*>(dst + i) = p;
}

// ---------------------------------------------------------------------------
// fp16 tensor-core GEMM (m16n8k16, fp32 accumulate); cp.async pipeline;
// ldmatrix fragments on both operands.
//   C[m,n] = alpha * sum_k A[m,k]*B(k,n) (+ bias[n])
//   TRB=false: B is [K,N] row-major (ldsm_x2_trans).
//   TRB=true : B is [N,K] row-major (ldsm_x2).
//   OUT16: store C as fp16 (__half2), else fp32 (float2, with bias).
// 256 threads. M%BM==0, N%BN==0, K%BK==0, BK%16==0.
// STAGES==1 requires K==BK.
// ---------------------------------------------------------------------------
template<int BM, int BN, int BK, int STAGES, int WR, int WC,
         bool TRB, bool OUT16>
__global__ __launch_bounds__(256)
void hgemm_kernel(const __half* __restrict__ A,
                  const __half* __restrict__ B,
                  void*         __restrict__ Cv,
                  const float*  __restrict__ bias,
                  int K, int lda, int ldb, int ldc,
                  long aOuter, long aInner,
                  long bOuter, long bInner,
                  long cOuter, long cInner,
                  int innerDiv, float alpha)
{
    constexpr int NTH  = 256;
    constexpr int MT   = BM / (WR*16);
    constexpr int NT   = BN / (WC*8);
    constexpr int ALD  = BK + 8;
    constexpr int BLD  = TRB ? (BK + 8) : (BN + 8);
    constexpr int BROW = TRB ? BN : BK;
    constexpr int ASZ  = BM * ALD;
    constexpr int BSZ  = BROW * BLD;
    constexpr int KST  = BK / 16;

    extern __shared__ __half hsm[];
    const uint32_t smem_u32 = (uint32_t)__cvta_generic_to_shared(hsm);

    const int tid  = threadIdx.x;
    const int wid  = tid >> 5;
    const int lane = tid & 31;
    const int wr   = wid / WC;
    const int wc   = wid % WC;
    const int g    = lane >> 2;
    const int tq   = lane & 3;

    const int z  = blockIdx.z;
    const int zo = z / innerDiv;
    const int zi = z % innerDiv;
    A += zo*aOuter + zi*aInner;
    B += zo*bOuter + zi*bInner;

    float*  Cf = (float*)Cv  + zo*cOuter + zi*cInner;
    __half* Ch = (__half*)Cv + zo*cOuter + zi*cInner;

    const int row0 = blockIdx.y * BM;
    const int col0 = blockIdx.x * BN;
    const int mw   = wr * (MT*16);
    const int nw   = wc * (NT*8);

    // ---- ldmatrix per-lane byte offsets ---------------------------------
    uint32_t aOff[MT];
    #pragma unroll
    for (int mt = 0; mt < MT; mt++)
        aOff[mt] = (uint32_t)((mw + mt*16 + ((lane>>3)&1)*8 + (lane&7))*ALD
                              + ((lane>>4)&1)*8) * 2;
    uint32_t bOff[NT];
    #pragma unroll
    for (int nt = 0; nt < NT; nt++) {
        if (TRB)
            bOff[nt] = (uint32_t)((nw + nt*8 + (lane&7))*BLD
                                  + ((lane>>3)&1)*8) * 2;
        else
            bOff[nt] = (uint32_t)((lane & 15)*BLD + nw + nt*8) * 2;
    }

    // ---- cp.async addressing (8 halves = 16B per op) --------------------
    constexpr int A_TPR   = BK/8;
    constexpr int A_RSTEP = NTH / A_TPR;
    constexpr int AITER   = BM / A_RSTEP;
    const int aRow = tid / A_TPR;
    const int aC8  = (tid % A_TPR) * 8;
    const __half* aBase = A + (long)(row0 + aRow)*lda + aC8;
    const int aSm0 = aRow*ALD + aC8;

    constexpr int B_TPR   = TRB ? (BK/8) : (BN/8);
    constexpr int B_RSTEP = NTH / B_TPR;
    constexpr int BITER   = (TRB ? BN : BK) / B_RSTEP;
    int bSm0;
    const __half* bBase;
    if (!TRB) {
        const int bKr = tid / B_TPR;
        const int bC8 = (tid % B_TPR) * 8;
        bBase = B + (long)bKr*ldb + col0 + bC8;
        bSm0  = bKr*BLD + bC8;
    } else {
        const int bN  = tid / B_TPR;
        const int bC8 = (tid % B_TPR) * 8;
        bBase = B + (long)(col0 + bN)*ldb + bC8;
        bSm0  = bN*BLD + bC8;
    }

    auto issue = [&](int kt, int s) {
        const int k0 = kt * BK;
        __half* AsS = hsm + s*ASZ;
        __half* BsS = hsm + STAGES*ASZ + s*BSZ;
        #pragma unroll
        for (int r = 0; r < AITER; r++)
            cpasync16(&AsS[aSm0 + r*A_RSTEP*ALD],
                      aBase + (long)r*A_RSTEP*lda + k0);
        if (!TRB) {
            #pragma unroll
            for (int r = 0; r < BITER; r++)
                cpasync16(&BsS[bSm0 + r*B_RSTEP*BLD],
                          bBase + (long)(k0 + r*B_RSTEP)*ldb);
        } else {
            #pragma unroll
            for (int r = 0; r < BITER; r++)
                cpasync16(&BsS[bSm0 + r*B_RSTEP*BLD],
                          bBase + (long)r*B_RSTEP*ldb + k0);
        }
    };

    float d[MT][NT][4];
    #pragma unroll
    for (int i = 0; i < MT; i++)
        #pragma unroll
        for (int j = 0; j < NT; j++)
            #pragma unroll
            for (int r = 0; r < 4; r++) d[i][j][r] = 0.f;

    const int nk = K / BK;

    auto compute = [&](int s) {
        const uint32_t aStage = smem_u32 + (uint32_t)(s*ASZ)*2;
        const uint32_t bStage = smem_u32 + (uint32_t)(STAGES*ASZ + s*BSZ)*2;
        #pragma unroll
        for (int kk = 0; kk < KST; kk++) {
            uint32_t a[MT][4], b[NT][2];
            #pragma unroll
            for (int mt = 0; mt < MT; mt++)
                ldsm_x4(a[mt], aStage + aOff[mt] + kk*32);
            #pragma unroll
            for (int nt = 0; nt < NT; nt++) {
                if (TRB)
                    ldsm_x2(b[nt], bStage + bOff[nt] + kk*32);
                else
                    ldsm_x2_trans(b[nt], bStage + bOff[nt] + kk*16*BLD*2);
            }
            #pragma unroll
            for (int mt = 0; mt < MT; mt++)
                #pragma unroll
                for (int nt = 0; nt < NT; nt++)
                    mma_f16(d[mt][nt], a[mt], b[nt]);
        }
    };

    if (STAGES == 1) {
        issue(0, 0);
        CP_COMMIT();
        cp_wait<0>();
        __syncthreads();
        compute(0);
    } else {
        constexpr int PRE = STAGES - 1;
        #pragma unroll
        for (int s = 0; s < PRE; s++) {
            if (s < nk) issue(s, s);
            CP_COMMIT();
        }
        for (int i = 0; i < nk; i++) {
            cp_wait<STAGES-2>();
            __syncthreads();
            compute(i % STAGES);
            if (i + PRE < nk) issue(i + PRE, (i + PRE) % STAGES);
            CP_COMMIT();
        }
    }

    // ---- epilogue ------------------------------------------------------
    #pragma unroll
    for (int mt = 0; mt < MT; mt++) {
        const int r0 = row0 + mw + mt*16 + g;
        #pragma unroll
        for (int nt = 0; nt < NT; nt++) {
            const int c = col0 + nw + nt*8 + tq*2;
            float e0 = alpha*d[mt][nt][0];
            float e1 = alpha*d[mt][nt][1];
            float e2 = alpha*d[mt][nt][2];
            float e3 = alpha*d[mt][nt][3];
            if (OUT16) {
                __half2 v0 = __floats2half2_rn(e0, e1);
                __half2 v1 = __floats2half2_rn(e2, e3);
                *reinterpret_cast<__half2*>(&Ch[(long)r0*ldc + c])     = v0;
                *reinterpret_cast<__half2*>(&Ch[(long)(r0+8)*ldc + c]) = v1;
            } else {
                if (bias) {
                    const float bx = bias[c], by = bias[c+1];
                    e0 += bx; e1 += by; e2 += bx; e3 += by;
                }
                float2 v0 = { e0, e1 };
                float2 v1 = { e2, e3 };
                *reinterpret_cast<float2*>(&Cf[(long)r0*ldc + c])     = v0;
                *reinterpret_cast<float2*>(&Cf[(long)(r0+8)*ldc + c]) = v1;
            }
        }
    }
}

// ---------------------------------------------------------------------------
// Fused softmax + cross-head remix + LayerNorm. One block per (b,i).
// Reads fp16 scores (exp/statistics in fp32); writes fp16 attention weights.
// ---------------------------------------------------------------------------
__global__ __launch_bounds__(256)
void softmax_remix_ln_kernel(const __half* __restrict__ attnA,
                             __half* __restrict__ attnB,
                             const float* __restrict__ W,
                             const float* __restrict__ gamma,
                             const float* __restrict__ beta)
{
    const int i = blockIdx.x;
    const int b = blockIdx.y;
    const int t = threadIdx.x;

    __shared__ float sW[HEADS_*HEADS_];
    __shared__ float sG[HEADS_], sBt[HEADS_];
    __shared__ float red[8][HEADS_];

    if (t < HEADS_*HEADS_) sW[t] = W[t];
    if (t < HEADS_) { sG[t] = gamma[t]; sBt[t] = beta[t]; }

    const long rowbase = (long)b * HEADS_ * NN + (long)i * SEQ_;

    float4 v[HEADS_];
    #pragma unroll
    for (int h = 0; h < HEADS_; h++) {
        uint2 p = *reinterpret_cast<const uint2*>(attnA + rowbase + (long)h*NN + t*4);
        __half2 lo = *reinterpret_cast<__half2*>(&p.x);
        __half2 hi = *reinterpret_cast<__half2*>(&p.y);
        float2 flo = __half22float2(lo);
        float2 fhi = __half22float2(hi);
        v[h] = make_float4(flo.x, flo.y, fhi.x, fhi.y);
    }

    #pragma unroll
    for (int h = 0; h < HEADS_; h++) {
        float m = fmaxf(fmaxf(v[h].x, v[h].y), fmaxf(v[h].z, v[h].w));
        #pragma unroll
        for (int o = 16; o > 0; o >>= 1)
            m = fmaxf(m, __shfl_xor_sync(0xffffffffu, m, o));
        if ((t & 31) == 0) red[t >> 5][h] = m;
    }
    __syncthreads();
    float gm[HEADS_];
    #pragma unroll
    for (int h = 0; h < HEADS_; h++) {
        float m = red[0][h];
        #pragma unroll
        for (int w = 1; w < 8; w++) m = fmaxf(m, red[w][h]);
        gm[h] = m;
    }
    __syncthreads();

    #pragma unroll
    for (int h = 0; h < HEADS_; h++) {
        v[h].x = __expf(v[h].x - gm[h]);
        v[h].y = __expf(v[h].y - gm[h]);
        v[h].z = __expf(v[h].z - gm[h]);
        v[h].w = __expf(v[h].w - gm[h]);
        float s = v[h].x + v[h].y + v[h].z + v[h].w;
        #pragma unroll
        for (int o = 16; o > 0; o >>= 1)
            s += __shfl_xor_sync(0xffffffffu, s, o);
        if ((t & 31) == 0) red[t >> 5][h] = s;
    }
    __syncthreads();
    float inv[HEADS_];
    #pragma unroll
    for (int h = 0; h < HEADS_; h++) {
        float s = red[0][h];
        #pragma unroll
        for (int w = 1; w < 8; w++) s += red[w][h];
        inv[h] = 1.f / s;
    }

    float4 outv[HEADS_];
    #pragma unroll
    for (int u = 0; u < 4; u++) {
        float p[HEADS_];
        #pragma unroll
        for (int h = 0; h < HEADS_; h++) {
            float pv = (u == 0) ? v[h].x : (u == 1) ? v[h].y
                     : (u == 2) ? v[h].z : v[h].w;
            p[h] = pv * inv[h];
        }
        float mixed[HEADS_];
        float mu = 0.f;
        #pragma unroll
        for (int k = 0; k < HEADS_; k++) {
            float s = 0.f;
            #pragma unroll
            for (int h = 0; h < HEADS_; h++) s += p[h] * sW[h*HEADS_ + k];
            mixed[k] = s;
            mu += s;
        }
        mu *= (1.f / HEADS_);
        float var = 0.f;
        #pragma unroll
        for (int k = 0; k < HEADS_; k++) {
            const float dd = mixed[k] - mu;
            var += dd * dd;
        }
        var *= (1.f / HEADS_);
        const float ninv = rsqrtf(var + EPS_);

        #pragma unroll
        for (int k = 0; k < HEADS_; k++) {
            float r = (mixed[k] - mu) * ninv * sG[k] + sBt[k];
            if      (u == 0) outv[k].x = r;
            else if (u == 1) outv[k].y = r;
            else if (u == 2) outv[k].z = r;
            else             outv[k].w = r;
        }
    }
    #pragma unroll
    for (int k = 0; k < HEADS_; k++) {
        __half2 lo = __floats2half2_rn(outv[k].x, outv[k].y);
        __half2 hi = __floats2half2_rn(outv[k].z, outv[k].w);
        uint2 packed = { *reinterpret_cast<uint32_t*>(&lo),
                         *reinterpret_cast<uint32_t*>(&hi) };
        *reinterpret_cast<uint2*>(attnB + rowbase + (long)k*NN + t*4) = packed;
    }
}

// ---------------------------------------------------------------------------
// Host launcher
// ---------------------------------------------------------------------------
extern "C" void kernel_launch(void* const* d_in, const int* in_sizes, int n_in,
                              void* d_out, int out_size)
{
    const float* x       = (const float*)d_in[0];
    const float* w_qkv   = (const float*)d_in[1];
    const float* reattnW = (const float*)d_in[2];
    const float* gamma   = (const float*)d_in[3];
    const float* beta    = (const float*)d_in[4];
    const float* w_out   = (const float*)d_in[5];
    const float* b_out   = (const float*)d_in[6];
    float* out = (float*)d_out;

    __half *xh, *wqkvh, *wouth, *qkvh, *attnA, *attnB, *outh;
    cudaGetSymbolAddress((void**)&xh,    g_xh);
    cudaGetSymbolAddress((void**)&wqkvh, g_wqkvh);
    cudaGetSymbolAddress((void**)&wouth, g_wouth);
    cudaGetSymbolAddress((void**)&qkvh,  g_qkvh);
    cudaGetSymbolAddress((void**)&attnA, g_attnA);
    cudaGetSymbolAddress((void**)&attnB, g_attnB);
    cudaGetSymbolAddress((void**)&outh,  g_outh);

    const float scale = 0.125f;

    // smem bytes: STAGES*(BM*(BK+8) + BROW*BLD)*2
    constexpr int SM_QKV  = 3 * (128*40 + 32*136) * 2;   // 56,832
    constexpr int SM_DOTS = 1 * (128*72 + 128*72) * 2;   // 36,864
    constexpr int SM_AV   = 3 * (128*40 + 32*72)  * 2;   // 44,544
    constexpr int SM_OUT  = SM_QKV;

    // 0) fp32 -> fp16 conversions
    f2h_kernel<<<(TOK*DIM_)/1024,    256>>>(x,     xh);
    f2h_kernel<<<(DIM_*QKVW)/1024,   256>>>(w_qkv, wqkvh);
    f2h_kernel<<<(INNER_*DIM_)/1024, 256>>>(w_out, wouth);

    // 1) qkvh = xh @ wqkvh (fp16 out)
    {
        auto k = hgemm_kernel<128,128,32,3,2,4,false,true>;
        cudaFuncSetAttribute(k, cudaFuncAttributeMaxDynamicSharedMemorySize, SM_QKV);
        dim3 grid(QKVW/128, TOK/128, 1);
        k<<<grid, 256, SM_QKV>>>(
            xh, wqkvh, qkvh, nullptr,
            DIM_, DIM_, QKVW, QKVW,
            0,0, 0,0, 0,0, 1, 1.f);
    }

    // 2) dots = scale * Q K^T per (b,h): single-shot BK=64, fp16 scores out
    {
        auto k = hgemm_kernel<128,128,64,1,2,4,true,true>;
        cudaFuncSetAttribute(k, cudaFuncAttributeMaxDynamicSharedMemorySize, SM_DOTS);
        dim3 grid(SEQ_/128, SEQ_/128, B_*HEADS_);
        k<<<grid, 256, SM_DOTS>>>(
            qkvh, qkvh + INNER_, attnA, nullptr,
            DH_, QKVW, QKVW, SEQ_,
            (long)SEQ_*QKVW, DH_,
            (long)SEQ_*QKVW, DH_,
            (long)HEADS_*NN,  NN,
            HEADS_, scale);
    }

    // 3) softmax + remix + LN: fp16 scores -> fp16 weights
    {
        dim3 grid(SEQ_, B_);
        softmax_remix_ln_kernel<<<grid, 256>>>(attnA, attnB, reattnW, gamma, beta);
    }

    // 4) outh = attnB @ V per (b,h) (fp16 out)
    {
        auto k = hgemm_kernel<128,64,32,3,2,4,false,true>;
        cudaFuncSetAttribute(k, cudaFuncAttributeMaxDynamicSharedMemorySize, SM_AV);
        dim3 grid(1, SEQ_/128, B_*HEADS_);
        k<<<grid, 256, SM_AV>>>(
            attnB, qkvh + 2*INNER_, outh, nullptr,
            SEQ_, SEQ_, QKVW, INNER_,
            (long)HEADS_*NN, NN,
            (long)SEQ_*QKVW, DH_,
            (long)SEQ_*INNER_, DH_,
            HEADS_, 1.f);
    }

    // 5) out = outh @ wouth + b_out (fp32 out)
    {
        auto k = hgemm_kernel<128,128,32,3,2,4,false,false>;
        cudaFuncSetAttribute(k, cudaFuncAttributeMaxDynamicSharedMemorySize, SM_OUT);
        dim3 grid(DIM_/128, TOK/128, 1);
        k<<<grid, 256, SM_OUT>>>(
            outh, wouth, out, b_out,
            INNER_, INNER_, DIM_, DIM_,
            0,0, 0,0, 0,0, 1, 1.f);
    }
}

// round 13
// speedup vs baseline: 1.6726x; 1.0078x over previous
#include <cuda_runtime.h>
#include <cuda_fp16.h>
#include <cstdint>

#define DIM_    768
#define HEADS_  12
#define DH_     64
#define INNER_  768
#define B_      4
#define SEQ_    1024
#define EPS_    1e-5f

static constexpr int  TOK  = B_ * SEQ_;          // 4096
static constexpr long NN   = (long)SEQ_ * SEQ_;  // 1M
static constexpr int  QKVW = 3 * INNER_;         // 2304

// ---------------------------------------------------------------------------
// Scratch
// ---------------------------------------------------------------------------
__device__ __half  g_xh   [(size_t)TOK * DIM_];
__device__ __half  g_wqkvh[(size_t)DIM_ * QKVW];
__device__ __half  g_wouth[(size_t)INNER_ * DIM_];
__device__ __half  g_qkvh [(size_t)TOK * QKVW];
__device__ __half  g_attnA[(size_t)B_ * HEADS_ * SEQ_ * SEQ_];   // fp16 scores
__device__ __half  g_attnB[(size_t)B_ * HEADS_ * SEQ_ * SEQ_];   // fp16 weights
__device__ __half  g_outh [(size_t)TOK * INNER_];

// ---------------------------------------------------------------------------
// helpers
// ---------------------------------------------------------------------------
__device__ __forceinline__ void mma_f16(float (&d)[4],
                                        const uint32_t (&a)[4],
                                        const uint32_t (&b)[2]) {
    asm volatile(
        "mma.sync.aligned.m16n8k16.row.col.f32.f16.f16.f32 "
        "{%0,%1,%2,%3}, {%4,%5,%6,%7}, {%8,%9}, {%0,%1,%2,%3};\n"
        : "+f"(d[0]), "+f"(d[1]), "+f"(d[2]), "+f"(d[3])
        : "r"(a[0]), "r"(a[1]), "r"(a[2]), "r"(a[3]),
          "r"(b[0]), "r"(b[1]));
}

__device__ __forceinline__ void ldsm_x4(uint32_t (&r)[4], uint32_t saddr) {
    asm volatile(
        "ldmatrix.sync.aligned.m8n8.x4.shared.b16 {%0,%1,%2,%3}, [%4];\n"
        : "=r"(r[0]), "=r"(r[1]), "=r"(r[2]), "=r"(r[3]) : "r"(saddr));
}
__device__ __forceinline__ void ldsm_x2(uint32_t (&r)[2], uint32_t saddr) {
    asm volatile(
        "ldmatrix.sync.aligned.m8n8.x2.shared.b16 {%0,%1}, [%2];\n"
        : "=r"(r[0]), "=r"(r[1]) : "r"(saddr));
}
__device__ __forceinline__ void ldsm_x2_trans(uint32_t (&r)[2], uint32_t saddr) {
    asm volatile(
        "ldmatrix.sync.aligned.m8n8.x2.trans.shared.b16 {%0,%1}, [%2];\n"
        : "=r"(r[0]), "=r"(r[1]) : "r"(saddr));
}

__device__ __forceinline__ void cpasync16(void* smem, const void* gmem) {
    uint32_t s = (uint32_t)__cvta_generic_to_shared(smem);
    asm volatile("cp.async.cg.shared.global [%0], [%1], 16;\n"
                 :: "r"(s), "l"(gmem));
}
#define CP_COMMIT() asm volatile("cp.async.commit_group;\n" ::: "memory")
template<int N> __device__ __forceinline__ void cp_wait() {
    asm volatile("cp.async.wait_group %0;\n" :: "n"(N) : "memory");
}

// ---------------------------------------------------------------------------
// fp32 -> fp16 conversion
// ---------------------------------------------------------------------------
__global__ __launch_bounds__(256)
void f2h_kernel(const float* __restrict__ src, __half* __restrict__ dst)
{
    const long i = ((long)blockIdx.x * 256 + threadIdx.x) * 4;
    float4 v = *reinterpret_cast<const float4*>(src + i);
    __half2 lo = __floats2half2_rn(v.x, v.y);
    __half2 hi = __floats2half2_rn(v.z, v.w);
    uint2 p = { *reinterpret_cast<uint32_t*>(&lo),
                *reinterpret_cast<uint32_t*>(&hi) };
    *reinterpret_cast<uint2*>(dst + i) = p;
}

// ---------------------------------------------------------------------------
// fp16 tensor-core GEMM (m16n8k16, fp32 accumulate); cp.async pipeline;
// ldmatrix fragments; OUT16 path stages C in smem for coalesced 16B stores.
//   C[m,n] = alpha * sum_k A[m,k]*B(k,n) (+ bias[n] on fp32 path)
//   TRB=false: B is [K,N] row-major (ldsm_x2_trans).
//   TRB=true : B is [N,K] row-major (ldsm_x2).
// 256 threads. M%BM==0, N%BN==0, K%BK==0, BK%16==0. STAGES==1 requires K==BK.
// OUT16 requires smem >= BM*(BN+8)*2 bytes (true at all call sites).
// ---------------------------------------------------------------------------
template<int BM, int BN, int BK, int STAGES, int WR, int WC,
         bool TRB, bool OUT16>
__global__ __launch_bounds__(256)
void hgemm_kernel(const __half* __restrict__ A,
                  const __half* __restrict__ B,
                  void*         __restrict__ Cv,
                  const float*  __restrict__ bias,
                  int K, int lda, int ldb, int ldc,
                  long aOuter, long aInner,
                  long bOuter, long bInner,
                  long cOuter, long cInner,
                  int innerDiv, float alpha)
{
    constexpr int NTH  = 256;
    constexpr int MT   = BM / (WR*16);
    constexpr int NT   = BN / (WC*8);
    constexpr int ALD  = BK + 8;
    constexpr int BLD  = TRB ? (BK + 8) : (BN + 8);
    constexpr int BROW = TRB ? BN : BK;
    constexpr int ASZ  = BM * ALD;
    constexpr int BSZ  = BROW * BLD;
    constexpr int KST  = BK / 16;
    constexpr int CLD  = BN + 8;                  // halves, staged-C ld

    extern __shared__ __half hsm[];
    const uint32_t smem_u32 = (uint32_t)__cvta_generic_to_shared(hsm);

    const int tid  = threadIdx.x;
    const int wid  = tid >> 5;
    const int lane = tid & 31;
    const int wr   = wid / WC;
    const int wc   = wid % WC;
    const int g    = lane >> 2;
    const int tq   = lane & 3;

    const int z  = blockIdx.z;
    const int zo = z / innerDiv;
    const int zi = z % innerDiv;
    A += zo*aOuter + zi*aInner;
    B += zo*bOuter + zi*bInner;

    float*  Cf = (float*)Cv  + zo*cOuter + zi*cInner;
    __half* Ch = (__half*)Cv + zo*cOuter + zi*cInner;

    const int row0 = blockIdx.y * BM;
    const int col0 = blockIdx.x * BN;
    const int mw   = wr * (MT*16);
    const int nw   = wc * (NT*8);

    // ---- ldmatrix per-lane byte offsets ---------------------------------
    uint32_t aOff[MT];
    #pragma unroll
    for (int mt = 0; mt < MT; mt++)
        aOff[mt] = (uint32_t)((mw + mt*16 + ((lane>>3)&1)*8 + (lane&7))*ALD
                              + ((lane>>4)&1)*8) * 2;
    uint32_t bOff[NT];
    #pragma unroll
    for (int nt = 0; nt < NT; nt++) {
        if (TRB)
            bOff[nt] = (uint32_t)((nw + nt*8 + (lane&7))*BLD
                                  + ((lane>>3)&1)*8) * 2;
        else
            bOff[nt] = (uint32_t)((lane & 15)*BLD + nw + nt*8) * 2;
    }

    // ---- cp.async addressing (8 halves = 16B per op) --------------------
    constexpr int A_TPR   = BK/8;
    constexpr int A_RSTEP = NTH / A_TPR;
    constexpr int AITER   = BM / A_RSTEP;
    const int aRow = tid / A_TPR;
    const int aC8  = (tid % A_TPR) * 8;
    const __half* aBase = A + (long)(row0 + aRow)*lda + aC8;
    const int aSm0 = aRow*ALD + aC8;

    constexpr int B_TPR   = TRB ? (BK/8) : (BN/8);
    constexpr int B_RSTEP = NTH / B_TPR;
    constexpr int BITER   = (TRB ? BN : BK) / B_RSTEP;
    int bSm0;
    const __half* bBase;
    if (!TRB) {
        const int bKr = tid / B_TPR;
        const int bC8 = (tid % B_TPR) * 8;
        bBase = B + (long)bKr*ldb + col0 + bC8;
        bSm0  = bKr*BLD + bC8;
    } else {
        const int bN  = tid / B_TPR;
        const int bC8 = (tid % B_TPR) * 8;
        bBase = B + (long)(col0 + bN)*ldb + bC8;
        bSm0  = bN*BLD + bC8;
    }

    auto issue = [&](int kt, int s) {
        const int k0 = kt * BK;
        __half* AsS = hsm + s*ASZ;
        __half* BsS = hsm + STAGES*ASZ + s*BSZ;
        #pragma unroll
        for (int r = 0; r < AITER; r++)
            cpasync16(&AsS[aSm0 + r*A_RSTEP*ALD],
                      aBase + (long)r*A_RSTEP*lda + k0);
        if (!TRB) {
            #pragma unroll
            for (int r = 0; r < BITER; r++)
                cpasync16(&BsS[bSm0 + r*B_RSTEP*BLD],
                          bBase + (long)(k0 + r*B_RSTEP)*ldb);
        } else {
            #pragma unroll
            for (int r = 0; r < BITER; r++)
                cpasync16(&BsS[bSm0 + r*B_RSTEP*BLD],
                          bBase + (long)r*B_RSTEP*ldb + k0);
        }
    };

    float d[MT][NT][4];
    #pragma unroll
    for (int i = 0; i < MT; i++)
        #pragma unroll
        for (int j = 0; j < NT; j++)
            #pragma unroll
            for (int r = 0; r < 4; r++) d[i][j][r] = 0.f;

    const int nk = K / BK;

    auto compute = [&](int s) {
        const uint32_t aStage = smem_u32 + (uint32_t)(s*ASZ)*2;
        const uint32_t bStage = smem_u32 + (uint32_t)(STAGES*ASZ + s*BSZ)*2;
        #pragma unroll
        for (int kk = 0; kk < KST; kk++) {
            uint32_t a[MT][4], b[NT][2];
            #pragma unroll
            for (int mt = 0; mt < MT; mt++)
                ldsm_x4(a[mt], aStage + aOff[mt] + kk*32);
            #pragma unroll
            for (int nt = 0; nt < NT; nt++) {
                if (TRB)
                    ldsm_x2(b[nt], bStage + bOff[nt] + kk*32);
                else
                    ldsm_x2_trans(b[nt], bStage + bOff[nt] + kk*16*BLD*2);
            }
            #pragma unroll
            for (int mt = 0; mt < MT; mt++)
                #pragma unroll
                for (int nt = 0; nt < NT; nt++)
                    mma_f16(d[mt][nt], a[mt], b[nt]);
        }
    };

    if (STAGES == 1) {
        issue(0, 0);
        CP_COMMIT();
        cp_wait<0>();
        __syncthreads();
        compute(0);
    } else {
        constexpr int PRE = STAGES - 1;
        #pragma unroll
        for (int s = 0; s < PRE; s++) {
            if (s < nk) issue(s, s);
            CP_COMMIT();
        }
        for (int i = 0; i < nk; i++) {
            cp_wait<STAGES-2>();
            __syncthreads();
            compute(i % STAGES);
            if (i + PRE < nk) issue(i + PRE, (i + PRE) % STAGES);
            CP_COMMIT();
        }
    }

    // ---- epilogue ------------------------------------------------------
    if (OUT16) {
        // stage fp16 C tile in smem, then coalesced 16B stores
        __syncthreads();
        #pragma unroll
        for (int mt = 0; mt < MT; mt++) {
            const int r = mw + mt*16 + g;
            #pragma unroll
            for (int nt = 0; nt < NT; nt++) {
                const int c = nw + nt*8 + tq*2;
                __half2 v0 = __floats2half2_rn(alpha*d[mt][nt][0],
                                               alpha*d[mt][nt][1]);
                __half2 v1 = __floats2half2_rn(alpha*d[mt][nt][2],
                                               alpha*d[mt][nt][3]);
                *reinterpret_cast<__half2*>(&hsm[ r     *CLD + c]) = v0;
                *reinterpret_cast<__half2*>(&hsm[(r + 8)*CLD + c]) = v1;
            }
        }
        __syncthreads();
        constexpr int TPR = BN / 8;           // threads per row (8 halves each)
        constexpr int RPI = NTH / TPR;        // rows per iteration
        const int cr = tid / TPR;
        const int cc = (tid % TPR) * 8;
        #pragma unroll
        for (int r = 0; r < BM; r += RPI) {
            uint4 v = *reinterpret_cast<uint4*>(&hsm[(cr + r)*CLD + cc]);
            *reinterpret_cast<uint4*>(
                &Ch[(long)(row0 + cr + r)*ldc + col0 + cc]) = v;
        }
    } else {
        #pragma unroll
        for (int mt = 0; mt < MT; mt++) {
            const int r0 = row0 + mw + mt*16 + g;
            #pragma unroll
            for (int nt = 0; nt < NT; nt++) {
                const int c = col0 + nw + nt*8 + tq*2;
                float e0 = alpha*d[mt][nt][0];
                float e1 = alpha*d[mt][nt][1];
                float e2 = alpha*d[mt][nt][2];
                float e3 = alpha*d[mt][nt][3];
                if (bias) {
                    const float bx = bias[c], by = bias[c+1];
                    e0 += bx; e1 += by; e2 += bx; e3 += by;
                }
                float2 v0 = { e0, e1 };
                float2 v1 = { e2, e3 };
                *reinterpret_cast<float2*>(&Cf[(long)r0*ldc + c])     = v0;
                *reinterpret_cast<float2*>(&Cf[(long)(r0+8)*ldc + c]) = v1;
            }
        }
    }
}

// ---------------------------------------------------------------------------
// Fused softmax + cross-head remix + LayerNorm. One block per (b,i).
// Reads fp16 scores (exp/statistics in fp32); writes fp16 attention weights.
// ---------------------------------------------------------------------------
__global__ __launch_bounds__(256)
void softmax_remix_ln_kernel(const __half* __restrict__ attnA,
                             __half* __restrict__ attnB,
                             const float* __restrict__ W,
                             const float* __restrict__ gamma,
                             const float* __restrict__ beta)
{
    const int i = blockIdx.x;
    const int b = blockIdx.y;
    const int t = threadIdx.x;

    __shared__ float sW[HEADS_*HEADS_];
    __shared__ float sG[HEADS_], sBt[HEADS_];
    __shared__ float red[8][HEADS_];

    if (t < HEADS_*HEADS_) sW[t] = W[t];
    if (t < HEADS_) { sG[t] = gamma[t]; sBt[t] = beta[t]; }

    const long rowbase = (long)b * HEADS_ * NN + (long)i * SEQ_;

    float4 v[HEADS_];
    #pragma unroll
    for (int h = 0; h < HEADS_; h++) {
        uint2 p = *reinterpret_cast<const uint2*>(attnA + rowbase + (long)h*NN + t*4);
        __half2 lo = *reinterpret_cast<__half2*>(&p.x);
        __half2 hi = *reinterpret_cast<__half2*>(&p.y);
        float2 flo = __half22float2(lo);
        float2 fhi = __half22float2(hi);
        v[h] = make_float4(flo.x, flo.y, fhi.x, fhi.y);
    }

    #pragma unroll
    for (int h = 0; h < HEADS_; h++) {
        float m = fmaxf(fmaxf(v[h].x, v[h].y), fmaxf(v[h].z, v[h].w));
        #pragma unroll
        for (int o = 16; o > 0; o >>= 1)
            m = fmaxf(m, __shfl_xor_sync(0xffffffffu, m, o));
        if ((t & 31) == 0) red[t >> 5][h] = m;
    }
    __syncthreads();
    float gm[HEADS_];
    #pragma unroll
    for (int h = 0; h < HEADS_; h++) {
        float m = red[0][h];
        #pragma unroll
        for (int w = 1; w < 8; w++) m = fmaxf(m, red[w][h]);
        gm[h] = m;
    }
    __syncthreads();

    #pragma unroll
    for (int h = 0; h < HEADS_; h++) {
        v[h].x = __expf(v[h].x - gm[h]);
        v[h].y = __expf(v[h].y - gm[h]);
        v[h].z = __expf(v[h].z - gm[h]);
        v[h].w = __expf(v[h].w - gm[h]);
        float s = v[h].x + v[h].y + v[h].z + v[h].w;
        #pragma unroll
        for (int o = 16; o > 0; o >>= 1)
            s += __shfl_xor_sync(0xffffffffu, s, o);
        if ((t & 31) == 0) red[t >> 5][h] = s;
    }
    __syncthreads();
    float inv[HEADS_];
    #pragma unroll
    for (int h = 0; h < HEADS_; h++) {
        float s = red[0][h];
        #pragma unroll
        for (int w = 1; w < 8; w++) s += red[w][h];
        inv[h] = 1.f / s;
    }

    float4 outv[HEADS_];
    #pragma unroll
    for (int u = 0; u < 4; u++) {
        float p[HEADS_];
        #pragma unroll
        for (int h = 0; h < HEADS_; h++) {
            float pv = (u == 0) ? v[h].x : (u == 1) ? v[h].y
                     : (u == 2) ? v[h].z : v[h].w;
            p[h] = pv * inv[h];
        }
        float mixed[HEADS_];
        float mu = 0.f;
        #pragma unroll
        for (int k = 0; k < HEADS_; k++) {
            float s = 0.f;
            #pragma unroll
            for (int h = 0; h < HEADS_; h++) s += p[h] * sW[h*HEADS_ + k];
            mixed[k] = s;
            mu += s;
        }
        mu *= (1.f / HEADS_);
        float var = 0.f;
        #pragma unroll
        for (int k = 0; k < HEADS_; k++) {
            const float dd = mixed[k] - mu;
            var += dd * dd;
        }
        var *= (1.f / HEADS_);
        const float ninv = rsqrtf(var + EPS_);

        #pragma unroll
        for (int k = 0; k < HEADS_; k++) {
            float r = (mixed[k] - mu) * ninv * sG[k] + sBt[k];
            if      (u == 0) outv[k].x = r;
            else if (u == 1) outv[k].y = r;
            else if (u == 2) outv[k].z = r;
            else             outv[k].w = r;
        }
    }
    #pragma unroll
    for (int k = 0; k < HEADS_; k++) {
        __half2 lo = __floats2half2_rn(outv[k].x, outv[k].y);
        __half2 hi = __floats2half2_rn(outv[k].z, outv[k].w);
        uint2 packed = { *reinterpret_cast<uint32_t*>(&lo),
                         *reinterpret_cast<uint32_t*>(&hi) };
        *reinterpret_cast<uint2*>(attnB + rowbase + (long)k*NN + t*4) = packed;
    }
}

// ---------------------------------------------------------------------------
// Host launcher
// ---------------------------------------------------------------------------
extern "C" void kernel_launch(void* const* d_in, const int* in_sizes, int n_in,
                              void* d_out, int out_size)
{
    const float* x       = (const float*)d_in[0];
    const float* w_qkv   = (const float*)d_in[1];
    const float* reattnW = (const float*)d_in[2];
    const float* gamma   = (const float*)d_in[3];
    const float* beta    = (const float*)d_in[4];
    const float* w_out   = (const float*)d_in[5];
    const float* b_out   = (const float*)d_in[6];
    float* out = (float*)d_out;

    __half *xh, *wqkvh, *wouth, *qkvh, *attnA, *attnB, *outh;
    cudaGetSymbolAddress((void**)&xh,    g_xh);
    cudaGetSymbolAddress((void**)&wqkvh, g_wqkvh);
    cudaGetSymbolAddress((void**)&wouth, g_wouth);
    cudaGetSymbolAddress((void**)&qkvh,  g_qkvh);
    cudaGetSymbolAddress((void**)&attnA, g_attnA);
    cudaGetSymbolAddress((void**)&attnB, g_attnB);
    cudaGetSymbolAddress((void**)&outh,  g_outh);

    const float scale = 0.125f;

    // smem bytes: max(pipeline, staged-C) per config
    // pipeline: STAGES*(BM*(BK+8) + BROW*BLD)*2 ; staged-C: BM*(BN+8)*2
    constexpr int SM_QKV  = 3 * (128*40 + 32*136) * 2;   // 56,832  (C stage 34,816)
    constexpr int SM_DOTS = 1 * (128*72 + 128*72) * 2;   // 36,864  (C stage 34,816)
    constexpr int SM_AV   = 3 * (128*40 + 32*72)  * 2;   // 44,544  (C stage 18,432)
    constexpr int SM_OUT  = SM_QKV;

    // 0) fp32 -> fp16 conversions
    f2h_kernel<<<(TOK*DIM_)/1024,    256>>>(x,     xh);
    f2h_kernel<<<(DIM_*QKVW)/1024,   256>>>(w_qkv, wqkvh);
    f2h_kernel<<<(INNER_*DIM_)/1024, 256>>>(w_out, wouth);

    // 1) qkvh = xh @ wqkvh (fp16 out, staged epilogue)
    {
        auto k = hgemm_kernel<128,128,32,3,2,4,false,true>;
        cudaFuncSetAttribute(k, cudaFuncAttributeMaxDynamicSharedMemorySize, SM_QKV);
        dim3 grid(QKVW/128, TOK/128, 1);
        k<<<grid, 256, SM_QKV>>>(
            xh, wqkvh, qkvh, nullptr,
            DIM_, DIM_, QKVW, QKVW,
            0,0, 0,0, 0,0, 1, 1.f);
    }

    // 2) dots = scale * Q K^T per (b,h): single-shot BK=64, fp16 scores out
    {
        auto k = hgemm_kernel<128,128,64,1,2,4,true,true>;
        cudaFuncSetAttribute(k, cudaFuncAttributeMaxDynamicSharedMemorySize, SM_DOTS);
        dim3 grid(SEQ_/128, SEQ_/128, B_*HEADS_);
        k<<<grid, 256, SM_DOTS>>>(
            qkvh, qkvh + INNER_, attnA, nullptr,
            DH_, QKVW, QKVW, SEQ_,
            (long)SEQ_*QKVW, DH_,
            (long)SEQ_*QKVW, DH_,
            (long)HEADS_*NN,  NN,
            HEADS_, scale);
    }

    // 3) softmax + remix + LN: fp16 scores -> fp16 weights
    {
        dim3 grid(SEQ_, B_);
        softmax_remix_ln_kernel<<<grid, 256>>>(attnA, attnB, reattnW, gamma, beta);
    }

    // 4) outh = attnB @ V per (b,h) (fp16 out, staged epilogue)
    {
        auto k = hgemm_kernel<128,64,32,3,2,4,false,true>;
        cudaFuncSetAttribute(k, cudaFuncAttributeMaxDynamicSharedMemorySize, SM_AV);
        dim3 grid(1, SEQ_/128, B_*HEADS_);
        k<<<grid, 256, SM_AV>>>(
            attnB, qkvh + 2*INNER_, outh, nullptr,
            SEQ_, SEQ_, QKVW, INNER_,
            (long)HEADS_*NN, NN,
            (long)SEQ_*QKVW, DH_,
            (long)SEQ_*INNER_, DH_,
            HEADS_, 1.f);
    }

    // 5) out = outh @ wouth + b_out (fp32 out)
    {
        auto k = hgemm_kernel<128,128,32,3,2,4,false,false>;
        cudaFuncSetAttribute(k, cudaFuncAttributeMaxDynamicSharedMemorySize, SM_OUT);
        dim3 grid(DIM_/128, TOK/128, 1);
        k<<<grid, 256, SM_OUT>>>(
            outh, wouth, out, b_out,
            INNER_, INNER_, DIM_, DIM_,
            0,0, 0,0, 0,0, 1, 1.f);
    }
}